// round 1
// baseline (speedup 1.0000x reference)
#include <cuda_runtime.h>
#include <math.h>

#define F_IN   128
#define H      64
#define HV     16          // float4 chunks per feature row
#define N_MAX  100000
#define G_MAX  4096
#define BN_EPS 1e-5f

// ---------------- scratch (device globals: allocation-free) ----------------
__device__ float4 g_bufA[(size_t)N_MAX * HV];
__device__ float4 g_bufB[(size_t)N_MAX * HV];
__device__ float4 g_agg [(size_t)N_MAX * HV];
__device__ float4 g_pooled[(size_t)G_MAX * HV];
__device__ float  g_dinv[N_MAX];

// ---------------- helpers ----------------
__device__ __forceinline__ void red_add_v4(float4* p, float4 v) {
    asm volatile("red.global.add.v4.f32 [%0], {%1, %2, %3, %4};"
                 :: "l"(p), "f"(v.x), "f"(v.y), "f"(v.z), "f"(v.w)
                 : "memory");
}

// ---------------- kernels ----------------
__global__ __launch_bounds__(256) void k_init(float4* agg, float4* pooled,
                                              float* deg, int n, int g) {
    int i = blockIdx.x * 256 + threadIdx.x;
    float4 z = make_float4(0.f, 0.f, 0.f, 0.f);
    if (i < n * HV) agg[i] = z;
    if (i < g * HV) pooled[i] = z;
    if (i < n)      deg[i] = 1.0f;       // self-loop contributes 1 to in-degree
}

__global__ __launch_bounds__(256) void k_deg(const int* __restrict__ dst,
                                             float* deg, int e) {
    int i = blockIdx.x * 256 + threadIdx.x;
    if (i < e) atomicAdd(deg + __ldg(dst + i), 1.0f);
}

__global__ __launch_bounds__(256) void k_rsqrt(float* d, int n) {
    int i = blockIdx.x * 256 + threadIdx.x;
    if (i < n) d[i] = rsqrtf(d[i]);      // deg >= 1 always
}

// C[n,64] = X[n,K] @ W[K,64], fp32 SIMT, 64-row block, 4x4 register tile.
template<int K>
__global__ __launch_bounds__(256) void k_gemm(const float* __restrict__ X,
                                              const float* __restrict__ W,
                                              float* __restrict__ Y, int n) {
    __shared__ float Xs[64][68];     // +4 pad: conflict-free, keeps 16B align
    __shared__ float Ws[64][H];
    const int t = threadIdx.x;
    const int row0 = blockIdx.x * 64;
    const int cx = t & 15;           // 16 col-groups of 4
    const int ry = t >> 4;           // 16 row-groups of 4

    float acc[4][4];
#pragma unroll
    for (int j = 0; j < 4; j++) {
        acc[j][0] = 0.f; acc[j][1] = 0.f; acc[j][2] = 0.f; acc[j][3] = 0.f;
    }

    for (int kb = 0; kb < K; kb += 64) {
        for (int idx = t; idx < 64 * H; idx += 256)
            Ws[idx >> 6][idx & 63] = W[(size_t)(kb + (idx >> 6)) * H + (idx & 63)];
        for (int idx = t; idx < 64 * 16; idx += 256) {
            int r = idx >> 4, kc = idx & 15;
            int gr = row0 + r;
            float4 v = make_float4(0.f, 0.f, 0.f, 0.f);
            if (gr < n) v = *(const float4*)(X + (size_t)gr * K + kb + kc * 4);
            *(float4*)&Xs[r][kc * 4] = v;
        }
        __syncthreads();

#pragma unroll 16
        for (int kk = 0; kk < 64; kk++) {
            float4 w = *(const float4*)&Ws[kk][cx * 4];
#pragma unroll
            for (int j = 0; j < 4; j++) {
                float xv = Xs[ry * 4 + j][kk];
                acc[j][0] += xv * w.x;
                acc[j][1] += xv * w.y;
                acc[j][2] += xv * w.z;
                acc[j][3] += xv * w.w;
            }
        }
        __syncthreads();
    }

#pragma unroll
    for (int j = 0; j < 4; j++) {
        int gr = row0 + ry * 4 + j;
        if (gr < n)
            *(float4*)(Y + (size_t)gr * H + cx * 4) =
                make_float4(acc[j][0], acc[j][1], acc[j][2], acc[j][3]);
    }
}

// 16 lanes per edge: coalesced 256B gather of h[src], normalized, vector-RED
// into agg[dst].
__global__ __launch_bounds__(256) void k_scatter(const int* __restrict__ src,
                                                 const int* __restrict__ dst,
                                                 const float* __restrict__ dinv,
                                                 const float4* __restrict__ h,
                                                 float4* agg, int e) {
    int gt = blockIdx.x * 256 + threadIdx.x;
    int eI = gt >> 4;
    if (eI >= e) return;
    int c = gt & 15;
    int s = __ldg(src + eI);
    int d = __ldg(dst + eI);
    float nr = __ldg(dinv + s) * __ldg(dinv + d);
    float4 v = __ldg(h + (size_t)s * HV + c);
    float4 r = make_float4(v.x * nr, v.y * nr, v.z * nr, v.w * nr);
    red_add_v4(agg + (size_t)d * HV + c, r);
}

// Fused epilogue: self-loop add + bias + eval-BN + ReLU, writes back into hbuf,
// optionally re-zeroes agg (for next layer) and/or pools into g_pooled.
template<bool ZERO, bool POOL>
__global__ __launch_bounds__(256) void k_post(float4* hbuf, float4* agg,
                                              const float* __restrict__ dinv,
                                              const float* __restrict__ bias,
                                              const float* __restrict__ gam,
                                              const float* __restrict__ bet,
                                              const float* __restrict__ rm,
                                              const float* __restrict__ rv,
                                              const int* __restrict__ batch,
                                              float4* pooled, int n) {
    int idx = blockIdx.x * 256 + threadIdx.x;
    if (idx >= n * HV) return;
    int i = idx >> 4, c = idx & 15;
    float4 a = agg[idx];
    float4 h = hbuf[idx];
    float di = __ldg(dinv + i);
    float d2 = di * di;
    int f = c * 4;
    float4 bb = *(const float4*)(bias + f);
    float4 gg = *(const float4*)(gam + f);
    float4 be = *(const float4*)(bet + f);
    float4 mm = *(const float4*)(rm + f);
    float4 vv = *(const float4*)(rv + f);
    float4 y;
    y.x = fmaxf((a.x + h.x * d2 + bb.x - mm.x) * (gg.x * rsqrtf(vv.x + BN_EPS)) + be.x, 0.f);
    y.y = fmaxf((a.y + h.y * d2 + bb.y - mm.y) * (gg.y * rsqrtf(vv.y + BN_EPS)) + be.y, 0.f);
    y.z = fmaxf((a.z + h.z * d2 + bb.z - mm.z) * (gg.z * rsqrtf(vv.z + BN_EPS)) + be.z, 0.f);
    y.w = fmaxf((a.w + h.w * d2 + bb.w - mm.w) * (gg.w * rsqrtf(vv.w + BN_EPS)) + be.w, 0.f);
    hbuf[idx] = y;
    if (ZERO) agg[idx] = make_float4(0.f, 0.f, 0.f, 0.f);
    if (POOL) {
        int gr = __ldg(batch + i);
        red_add_v4(pooled + (size_t)gr * HV + c, y);
    }
}

// Final MLP on pooled [g,64]: relu(@l1w+l1b) @ l2w + l2b -> out [g,2]
__global__ __launch_bounds__(256) void k_mlp(const float* __restrict__ pooled,
                                             const float* __restrict__ l1w,
                                             const float* __restrict__ l1b,
                                             const float* __restrict__ l2w,
                                             const float* __restrict__ l2b,
                                             float* __restrict__ out, int g) {
    __shared__ float4 W1[64 * 8];    // l1w [64,32] as float4 over cols
    __shared__ float  B1[32];
    __shared__ float  W2[64];        // l2w [32,2]
    __shared__ float  B2[2];
    int t = threadIdx.x;
    for (int idx = t; idx < 512; idx += 256) W1[idx] = ((const float4*)l1w)[idx];
    if (t < 32) B1[t] = l1b[t];
    if (t < 64) W2[t] = l2w[t];
    if (t < 2)  B2[t] = l2b[t];
    __syncthreads();

    int gi = blockIdx.x * 256 + t;
    if (gi >= g) return;

    float hid[32];
#pragma unroll
    for (int j = 0; j < 32; j++) hid[j] = B1[j];
    for (int k = 0; k < 64; k++) {
        float p = pooled[(size_t)gi * 64 + k];
#pragma unroll
        for (int jj = 0; jj < 8; jj++) {
            float4 w = W1[k * 8 + jj];
            hid[jj * 4 + 0] += p * w.x;
            hid[jj * 4 + 1] += p * w.y;
            hid[jj * 4 + 2] += p * w.z;
            hid[jj * 4 + 3] += p * w.w;
        }
    }
    float o0 = B2[0], o1 = B2[1];
#pragma unroll
    for (int j = 0; j < 32; j++) {
        float hj = fmaxf(hid[j], 0.f);
        o0 += hj * W2[j * 2 + 0];
        o1 += hj * W2[j * 2 + 1];
    }
    out[(size_t)gi * 2 + 0] = o0;
    out[(size_t)gi * 2 + 1] = o1;
}

// ---------------- launch ----------------
extern "C" void kernel_launch(void* const* d_in, const int* in_sizes, int n_in,
                              void* d_out, int out_size) {
    const float* x     = (const float*)d_in[0];
    const int*   ei    = (const int*)  d_in[1];
    const int*   batch = (const int*)  d_in[2];
    const float* w0 = (const float*)d_in[3];
    const float* b0 = (const float*)d_in[4];
    const float* w1 = (const float*)d_in[5];
    const float* b1 = (const float*)d_in[6];
    const float* w2 = (const float*)d_in[7];
    const float* b2 = (const float*)d_in[8];
    const float* gg0 = (const float*)d_in[9],  *be0 = (const float*)d_in[10];
    const float* m0  = (const float*)d_in[11], *v0  = (const float*)d_in[12];
    const float* gg1 = (const float*)d_in[13], *be1 = (const float*)d_in[14];
    const float* m1  = (const float*)d_in[15], *v1  = (const float*)d_in[16];
    const float* gg2 = (const float*)d_in[17], *be2 = (const float*)d_in[18];
    const float* m2  = (const float*)d_in[19], *v2  = (const float*)d_in[20];
    const float* l1w = (const float*)d_in[21], *l1b = (const float*)d_in[22];
    const float* l2w = (const float*)d_in[23], *l2b = (const float*)d_in[24];

    const int n = in_sizes[0] / F_IN;
    const int e = in_sizes[1] / 2;
    const int g = out_size / 2;
    if (n <= 0) return;

    float4 *bufA, *bufB, *agg, *pooled;
    float  *dinv;
    cudaGetSymbolAddress((void**)&bufA,   g_bufA);
    cudaGetSymbolAddress((void**)&bufB,   g_bufB);
    cudaGetSymbolAddress((void**)&agg,    g_agg);
    cudaGetSymbolAddress((void**)&pooled, g_pooled);
    cudaGetSymbolAddress((void**)&dinv,   g_dinv);

    const int* src = ei;
    const int* dst = ei + e;

    const int TB = 256;
    const int gElem   = (n * HV + TB - 1) / TB;   // n*16 float4 work items
    const int gEdge   = (e + TB - 1) / TB;
    const int gNode   = (n + TB - 1) / TB;
    const int gScat   = ((size_t)e * HV + TB - 1) / TB;
    const int gGemm   = (n + 63) / 64;

    // degree / normalization
    k_init <<<gElem, TB>>>(agg, pooled, dinv, n, g);
    k_deg  <<<gEdge, TB>>>(dst, dinv, e);
    k_rsqrt<<<gNode, TB>>>(dinv, n);

    // layer 0
    k_gemm<F_IN><<<gGemm, TB>>>(x, w0, (float*)bufA, n);
    k_scatter    <<<gScat, TB>>>(src, dst, dinv, bufA, agg, e);
    k_post<true, false><<<gElem, TB>>>(bufA, agg, dinv, b0, gg0, be0, m0, v0,
                                       batch, pooled, n);
    // layer 1
    k_gemm<H><<<gGemm, TB>>>((const float*)bufA, w1, (float*)bufB, n);
    k_scatter<<<gScat, TB>>>(src, dst, dinv, bufB, agg, e);
    k_post<true, false><<<gElem, TB>>>(bufB, agg, dinv, b1, gg1, be1, m1, v1,
                                       batch, pooled, n);
    // layer 2 (pool fused into epilogue)
    k_gemm<H><<<gGemm, TB>>>((const float*)bufB, w2, (float*)bufA, n);
    k_scatter<<<gScat, TB>>>(src, dst, dinv, bufA, agg, e);
    k_post<false, true><<<gElem, TB>>>(bufA, agg, dinv, b2, gg2, be2, m2, v2,
                                       batch, pooled, n);

    // readout MLP
    k_mlp<<<(g + TB - 1) / TB, TB>>>((const float*)pooled, l1w, l1b, l2w, l2b,
                                     (float*)d_out, g);
}

// round 2
// speedup vs baseline: 2.1939x; 2.1939x over previous
#include <cuda_runtime.h>
#include <math.h>

#define F_IN   128
#define H      64
#define HV     16          // float4 chunks per feature row
#define N_MAX  100000
#define E_MAX  1700000
#define G_MAX  4096
#define BN_EPS 1e-5f
#define SBS    1024

// ---------------- scratch (device globals: allocation-free) ----------------
__device__ float4 g_bufA[(size_t)N_MAX * HV];
__device__ float4 g_bufB[(size_t)N_MAX * HV];
__device__ float4 g_pooled[(size_t)G_MAX * HV];
__device__ float  g_dinv[N_MAX];
__device__ int    g_degcnt[N_MAX];
__device__ int    g_cursor[N_MAX];
__device__ int    g_incl[N_MAX];
__device__ int    g_bsum[SBS];
__device__ int    g_rowptr[N_MAX + 1];
__device__ int    g_csrc[E_MAX];
__device__ float  g_cw[E_MAX];
__device__ float  g_bnA[3 * H];
__device__ float  g_bnB[3 * H];

// ---------------- helpers ----------------
__device__ __forceinline__ void red_add_v4(float4* p, float4 v) {
    asm volatile("red.global.add.v4.f32 [%0], {%1, %2, %3, %4};"
                 :: "l"(p), "f"(v.x), "f"(v.y), "f"(v.z), "f"(v.w)
                 : "memory");
}

// ---------------- setup kernels ----------------
__global__ __launch_bounds__(256) void k_init(float4* pooled, int* degcnt,
                                              int* cursor, int n, int g) {
    int i = blockIdx.x * 256 + threadIdx.x;
    if (i < g * HV) pooled[i] = make_float4(0.f, 0.f, 0.f, 0.f);
    if (i < n) { degcnt[i] = 0; cursor[i] = 0; }
}

__global__ __launch_bounds__(256) void k_hist(const int* __restrict__ dst,
                                              int* degcnt, int e) {
    int i = blockIdx.x * 256 + threadIdx.x;
    if (i < e) atomicAdd(degcnt + __ldg(dst + i), 1);
}

__global__ __launch_bounds__(SBS) void k_scan1(const int* __restrict__ cnt,
                                               int* incl, int* bsum,
                                               float* dinv, int n) {
    __shared__ int sh[SBS];
    int i = blockIdx.x * SBS + threadIdx.x;
    int v = (i < n) ? cnt[i] : 0;
    if (i < n) dinv[i] = rsqrtf((float)v + 1.0f);   // + self-loop
    sh[threadIdx.x] = v;
    __syncthreads();
    for (int off = 1; off < SBS; off <<= 1) {
        int t = (threadIdx.x >= off) ? sh[threadIdx.x - off] : 0;
        __syncthreads();
        sh[threadIdx.x] += t;
        __syncthreads();
    }
    if (i < n) incl[i] = sh[threadIdx.x];
    if (threadIdx.x == SBS - 1) bsum[blockIdx.x] = sh[SBS - 1];
}

__global__ __launch_bounds__(SBS) void k_scan2(int* bsum, int nb) {
    __shared__ int sh[SBS];
    int t = threadIdx.x;
    int v = (t < nb) ? bsum[t] : 0;
    sh[t] = v;
    __syncthreads();
    for (int off = 1; off < SBS; off <<= 1) {
        int u = (t >= off) ? sh[t - off] : 0;
        __syncthreads();
        sh[t] += u;
        __syncthreads();
    }
    if (t < nb) bsum[t] = sh[t] - v;                // exclusive
}

__global__ __launch_bounds__(256) void k_scan3(const int* __restrict__ incl,
                                               const int* __restrict__ bsum,
                                               int* rowptr, int n) {
    int i = blockIdx.x * 256 + threadIdx.x;
    if (i < n) rowptr[i + 1] = incl[i] + bsum[i / SBS];
    if (i == 0) rowptr[0] = 0;
}

__global__ __launch_bounds__(256) void k_fill(const int* __restrict__ src,
                                              const int* __restrict__ dst,
                                              const int* __restrict__ rowptr,
                                              const float* __restrict__ dinv,
                                              int* cursor, int* csrc,
                                              float* cw, int e) {
    int i = blockIdx.x * 256 + threadIdx.x;
    if (i >= e) return;
    int s = __ldg(src + i), d = __ldg(dst + i);
    int pos = __ldg(rowptr + d) + atomicAdd(cursor + d, 1);
    csrc[pos] = s;
    cw[pos] = __ldg(dinv + s) * __ldg(dinv + d);
}

// Fold eval-BN + bias into per-feature affine: y = relu(agg_total*A + B)
__global__ void k_bn(const float* b0, const float* gg0, const float* be0,
                     const float* m0, const float* v0,
                     const float* b1, const float* gg1, const float* be1,
                     const float* m1, const float* v1,
                     const float* b2, const float* gg2, const float* be2,
                     const float* m2, const float* v2,
                     float* A, float* B) {
    int t = threadIdx.x;
    if (t >= 3 * H) return;
    int l = t >> 6, f = t & 63;
    const float* bs[3] = {b0, b1, b2};
    const float* gs[3] = {gg0, gg1, gg2};
    const float* es[3] = {be0, be1, be2};
    const float* ms[3] = {m0, m1, m2};
    const float* vs[3] = {v0, v1, v2};
    float a = gs[l][f] * rsqrtf(vs[l][f] + BN_EPS);
    A[t] = a;
    B[t] = es[l][f] + (bs[l][f] - ms[l][f]) * a;
}

// ---------------- GEMM: C[n,64] = X[n,K] @ W[K,64] ----------------
template<int K>
__global__ __launch_bounds__(256) void k_gemm(const float* __restrict__ X,
                                              const float* __restrict__ W,
                                              float* __restrict__ Y, int n) {
    __shared__ float Xs[64][68];     // row stride 272B: 16B-aligned, low-conflict
    __shared__ float Ws[64][H];
    const int t = threadIdx.x;
    const int row0 = blockIdx.x * 64;
    const int cx = t & 15;           // 16 col-groups of 4
    const int ry = t >> 4;           // 16 row-groups of 4

    float4 acc[4];
#pragma unroll
    for (int j = 0; j < 4; j++) acc[j] = make_float4(0.f, 0.f, 0.f, 0.f);

    for (int kb = 0; kb < K; kb += 64) {
        for (int idx = t; idx < 64 * H; idx += 256)
            Ws[idx >> 6][idx & 63] = W[(size_t)(kb + (idx >> 6)) * H + (idx & 63)];
        for (int idx = t; idx < 64 * 16; idx += 256) {
            int r = idx >> 4, kc = idx & 15;
            int gr = row0 + r;
            float4 v = make_float4(0.f, 0.f, 0.f, 0.f);
            if (gr < n) v = *(const float4*)(X + (size_t)gr * K + kb + kc * 4);
            *(float4*)&Xs[r][kc * 4] = v;
        }
        __syncthreads();

#pragma unroll
        for (int kk = 0; kk < 64; kk += 4) {
            float4 w0 = *(const float4*)&Ws[kk + 0][cx * 4];
            float4 w1 = *(const float4*)&Ws[kk + 1][cx * 4];
            float4 w2 = *(const float4*)&Ws[kk + 2][cx * 4];
            float4 w3 = *(const float4*)&Ws[kk + 3][cx * 4];
#pragma unroll
            for (int j = 0; j < 4; j++) {
                float4 xv = *(const float4*)&Xs[ry * 4 + j][kk];
                acc[j].x = fmaf(xv.x, w0.x, acc[j].x);
                acc[j].y = fmaf(xv.x, w0.y, acc[j].y);
                acc[j].z = fmaf(xv.x, w0.z, acc[j].z);
                acc[j].w = fmaf(xv.x, w0.w, acc[j].w);
                acc[j].x = fmaf(xv.y, w1.x, acc[j].x);
                acc[j].y = fmaf(xv.y, w1.y, acc[j].y);
                acc[j].z = fmaf(xv.y, w1.z, acc[j].z);
                acc[j].w = fmaf(xv.y, w1.w, acc[j].w);
                acc[j].x = fmaf(xv.z, w2.x, acc[j].x);
                acc[j].y = fmaf(xv.z, w2.y, acc[j].y);
                acc[j].z = fmaf(xv.z, w2.z, acc[j].z);
                acc[j].w = fmaf(xv.z, w2.w, acc[j].w);
                acc[j].x = fmaf(xv.w, w3.x, acc[j].x);
                acc[j].y = fmaf(xv.w, w3.y, acc[j].y);
                acc[j].z = fmaf(xv.w, w3.z, acc[j].z);
                acc[j].w = fmaf(xv.w, w3.w, acc[j].w);
            }
        }
        __syncthreads();
    }

#pragma unroll
    for (int j = 0; j < 4; j++) {
        int gr = row0 + ry * 4 + j;
        if (gr < n)
            *(float4*)(Y + (size_t)gr * H + cx * 4) = acc[j];
    }
}

// --------- fused gather-aggregate + self-loop + BN + ReLU (+pool) ----------
// Warp per node: 16 float4 columns x 2 edge slots; shfl-combine parities.
template<bool POOL>
__global__ __launch_bounds__(256) void k_gather(const int* __restrict__ rowptr,
                                                const int* __restrict__ csrc,
                                                const float* __restrict__ cw,
                                                const float* __restrict__ dinv,
                                                const float4* __restrict__ h,
                                                float4* __restrict__ y,
                                                const float* __restrict__ bnA,
                                                const float* __restrict__ bnB,
                                                const int* __restrict__ batch,
                                                float4* pooled, int n) {
    int node = blockIdx.x * 8 + (threadIdx.x >> 5);
    if (node >= n) return;
    int lane = threadIdx.x & 31;
    int c = lane & 15, p = lane >> 4;
    int beg = __ldg(rowptr + node), end = __ldg(rowptr + node + 1);

    float4 acc = make_float4(0.f, 0.f, 0.f, 0.f);
#pragma unroll 2
    for (int j = beg + p; j < end; j += 2) {
        int s = __ldg(csrc + j);
        float w = __ldg(cw + j);
        float4 v = __ldg(h + (size_t)s * HV + c);
        acc.x = fmaf(v.x, w, acc.x);
        acc.y = fmaf(v.y, w, acc.y);
        acc.z = fmaf(v.z, w, acc.z);
        acc.w = fmaf(v.w, w, acc.w);
    }
    acc.x += __shfl_down_sync(0xffffffffu, acc.x, 16);
    acc.y += __shfl_down_sync(0xffffffffu, acc.y, 16);
    acc.z += __shfl_down_sync(0xffffffffu, acc.z, 16);
    acc.w += __shfl_down_sync(0xffffffffu, acc.w, 16);

    if (p == 0) {
        float di = __ldg(dinv + node);
        float d2 = di * di;                       // self-loop weight
        float4 hv = __ldg(h + (size_t)node * HV + c);
        float4 A = *(const float4*)(bnA + c * 4);
        float4 B = *(const float4*)(bnB + c * 4);
        float4 o;
        o.x = fmaxf(fmaf(fmaf(hv.x, d2, acc.x), A.x, B.x), 0.f);
        o.y = fmaxf(fmaf(fmaf(hv.y, d2, acc.y), A.y, B.y), 0.f);
        o.z = fmaxf(fmaf(fmaf(hv.z, d2, acc.z), A.z, B.z), 0.f);
        o.w = fmaxf(fmaf(fmaf(hv.w, d2, acc.w), A.w, B.w), 0.f);
        y[(size_t)node * HV + c] = o;
        if (POOL)
            red_add_v4(pooled + (size_t)__ldg(batch + node) * HV + c, o);
    }
}

// ---------------- readout MLP ----------------
__global__ __launch_bounds__(256) void k_mlp(const float* __restrict__ pooled,
                                             const float* __restrict__ l1w,
                                             const float* __restrict__ l1b,
                                             const float* __restrict__ l2w,
                                             const float* __restrict__ l2b,
                                             float* __restrict__ out, int g) {
    __shared__ float4 W1[64 * 8];
    __shared__ float  B1[32];
    __shared__ float  W2[64];
    __shared__ float  B2[2];
    int t = threadIdx.x;
    for (int idx = t; idx < 512; idx += 256) W1[idx] = ((const float4*)l1w)[idx];
    if (t < 32) B1[t] = l1b[t];
    if (t < 64) W2[t] = l2w[t];
    if (t < 2)  B2[t] = l2b[t];
    __syncthreads();

    int gi = blockIdx.x * 256 + t;
    if (gi >= g) return;

    float hid[32];
#pragma unroll
    for (int j = 0; j < 32; j++) hid[j] = B1[j];
    for (int k = 0; k < 64; k++) {
        float p = pooled[(size_t)gi * 64 + k];
#pragma unroll
        for (int jj = 0; jj < 8; jj++) {
            float4 w = W1[k * 8 + jj];
            hid[jj * 4 + 0] = fmaf(p, w.x, hid[jj * 4 + 0]);
            hid[jj * 4 + 1] = fmaf(p, w.y, hid[jj * 4 + 1]);
            hid[jj * 4 + 2] = fmaf(p, w.z, hid[jj * 4 + 2]);
            hid[jj * 4 + 3] = fmaf(p, w.w, hid[jj * 4 + 3]);
        }
    }
    float o0 = B2[0], o1 = B2[1];
#pragma unroll
    for (int j = 0; j < 32; j++) {
        float hj = fmaxf(hid[j], 0.f);
        o0 = fmaf(hj, W2[j * 2 + 0], o0);
        o1 = fmaf(hj, W2[j * 2 + 1], o1);
    }
    out[(size_t)gi * 2 + 0] = o0;
    out[(size_t)gi * 2 + 1] = o1;
}

// ---------------- launch ----------------
extern "C" void kernel_launch(void* const* d_in, const int* in_sizes, int n_in,
                              void* d_out, int out_size) {
    const float* x     = (const float*)d_in[0];
    const int*   ei    = (const int*)  d_in[1];
    const int*   batch = (const int*)  d_in[2];
    const float* w0 = (const float*)d_in[3];
    const float* b0 = (const float*)d_in[4];
    const float* w1 = (const float*)d_in[5];
    const float* b1 = (const float*)d_in[6];
    const float* w2 = (const float*)d_in[7];
    const float* b2 = (const float*)d_in[8];
    const float* gg0 = (const float*)d_in[9],  *be0 = (const float*)d_in[10];
    const float* m0  = (const float*)d_in[11], *v0  = (const float*)d_in[12];
    const float* gg1 = (const float*)d_in[13], *be1 = (const float*)d_in[14];
    const float* m1  = (const float*)d_in[15], *v1  = (const float*)d_in[16];
    const float* gg2 = (const float*)d_in[17], *be2 = (const float*)d_in[18];
    const float* m2  = (const float*)d_in[19], *v2  = (const float*)d_in[20];
    const float* l1w = (const float*)d_in[21], *l1b = (const float*)d_in[22];
    const float* l2w = (const float*)d_in[23], *l2b = (const float*)d_in[24];

    const int n = in_sizes[0] / F_IN;
    const int e = in_sizes[1] / 2;
    const int g = out_size / 2;
    if (n <= 0) return;

    float4 *bufA, *bufB, *pooled;
    float  *dinv, *cw, *bnA, *bnB;
    int    *degcnt, *cursor, *incl, *bsum, *rowptr, *csrc;
    cudaGetSymbolAddress((void**)&bufA,   g_bufA);
    cudaGetSymbolAddress((void**)&bufB,   g_bufB);
    cudaGetSymbolAddress((void**)&pooled, g_pooled);
    cudaGetSymbolAddress((void**)&dinv,   g_dinv);
    cudaGetSymbolAddress((void**)&degcnt, g_degcnt);
    cudaGetSymbolAddress((void**)&cursor, g_cursor);
    cudaGetSymbolAddress((void**)&incl,   g_incl);
    cudaGetSymbolAddress((void**)&bsum,   g_bsum);
    cudaGetSymbolAddress((void**)&rowptr, g_rowptr);
    cudaGetSymbolAddress((void**)&csrc,   g_csrc);
    cudaGetSymbolAddress((void**)&cw,     g_cw);
    cudaGetSymbolAddress((void**)&bnA,    g_bnA);
    cudaGetSymbolAddress((void**)&bnB,    g_bnB);

    const int* src = ei;
    const int* dst = ei + e;

    const int TB = 256;
    const int gInit = (((n > g * HV) ? n : g * HV) + TB - 1) / TB;
    const int gEdge = (e + TB - 1) / TB;
    const int gNode = (n + TB - 1) / TB;
    const int nbScan = (n + SBS - 1) / SBS;
    const int gGemm = (n + 63) / 64;
    const int gGath = (n + 7) / 8;

    // ----- graph preprocessing: degrees, dinv, CSR by dst, edge weights -----
    k_init <<<gInit, TB>>>(pooled, degcnt, cursor, n, g);
    k_hist <<<gEdge, TB>>>(dst, degcnt, e);
    k_scan1<<<nbScan, SBS>>>(degcnt, incl, bsum, dinv, n);
    k_scan2<<<1, SBS>>>(bsum, nbScan);
    k_scan3<<<gNode, TB>>>(incl, bsum, rowptr, n);
    k_fill <<<gEdge, TB>>>(src, dst, rowptr, dinv, cursor, csrc, cw, e);
    k_bn   <<<1, 3 * H>>>(b0, gg0, be0, m0, v0, b1, gg1, be1, m1, v1,
                          b2, gg2, be2, m2, v2, bnA, bnB);

    // ----- layer 0 -----
    k_gemm<F_IN><<<gGemm, TB>>>(x, w0, (float*)bufA, n);
    k_gather<false><<<gGath, TB>>>(rowptr, csrc, cw, dinv, bufA, bufB,
                                   bnA, bnB, batch, pooled, n);
    // ----- layer 1 -----
    k_gemm<H><<<gGemm, TB>>>((const float*)bufB, w1, (float*)bufA, n);
    k_gather<false><<<gGath, TB>>>(rowptr, csrc, cw, dinv, bufA, bufB,
                                   bnA + H, bnB + H, batch, pooled, n);
    // ----- layer 2 (pool fused) -----
    k_gemm<H><<<gGemm, TB>>>((const float*)bufB, w2, (float*)bufA, n);
    k_gather<true><<<gGath, TB>>>(rowptr, csrc, cw, dinv, bufA, bufB,
                                  bnA + 2 * H, bnB + 2 * H, batch, pooled, n);

    // ----- readout MLP -----
    k_mlp<<<(g + TB - 1) / TB, TB>>>((const float*)pooled, l1w, l1b, l2w, l2b,
                                     (float*)d_out, g);
}

// round 3
// speedup vs baseline: 2.2052x; 1.0051x over previous
#include <cuda_runtime.h>
#include <math.h>

#define F_IN   128
#define H      64
#define HV     16          // float4 chunks per feature row
#define N_MAX  100000
#define E_MAX  1700000
#define G_MAX  4096
#define BN_EPS 1e-5f
#define SBS    1024
#define KB     32          // GEMM k-block

// ---------------- scratch (device globals: allocation-free) ----------------
__device__ float4 g_bufA[(size_t)N_MAX * HV];
__device__ float4 g_bufB[(size_t)N_MAX * HV];
__device__ float4 g_pooled[(size_t)G_MAX * HV];
__device__ float  g_dinv[N_MAX];
__device__ int    g_degcnt[N_MAX];
__device__ int    g_cursor[N_MAX];
__device__ int    g_incl[N_MAX];
__device__ int    g_bsum[SBS];
__device__ int    g_rowptr[N_MAX + 1];
__device__ int    g_csrc[E_MAX];
__device__ float  g_cw[E_MAX];
__device__ float  g_bnA[3 * H];
__device__ float  g_bnB[3 * H];

// ---------------- helpers ----------------
__device__ __forceinline__ void red_add_v4(float4* p, float4 v) {
    asm volatile("red.global.add.v4.f32 [%0], {%1, %2, %3, %4};"
                 :: "l"(p), "f"(v.x), "f"(v.y), "f"(v.z), "f"(v.w)
                 : "memory");
}

// packed fp32 FMA: d = a*b + d  (element-wise on two packed floats)
__device__ __forceinline__ void ffma2(unsigned long long& d,
                                      unsigned long long a,
                                      unsigned long long b) {
    asm("fma.rn.f32x2 %0, %1, %2, %0;" : "+l"(d) : "l"(a), "l"(b));
}
__device__ __forceinline__ float u64_lo(unsigned long long a) {
    return __uint_as_float((unsigned)(a & 0xffffffffull));
}
__device__ __forceinline__ float u64_hi(unsigned long long a) {
    return __uint_as_float((unsigned)(a >> 32));
}

// ---------------- setup kernels ----------------
__global__ __launch_bounds__(256) void k_init(float4* pooled, int* degcnt,
                                              int* cursor, int n, int g) {
    int i = blockIdx.x * 256 + threadIdx.x;
    if (i < g * HV) pooled[i] = make_float4(0.f, 0.f, 0.f, 0.f);
    if (i < n) { degcnt[i] = 0; cursor[i] = 0; }
}

__global__ __launch_bounds__(256) void k_hist(const int* __restrict__ dst,
                                              int* degcnt, int e) {
    int i = blockIdx.x * 256 + threadIdx.x;
    if (i < e) atomicAdd(degcnt + __ldg(dst + i), 1);
}

__global__ __launch_bounds__(SBS) void k_scan1(const int* __restrict__ cnt,
                                               int* incl, int* bsum,
                                               float* dinv, int n) {
    __shared__ int sh[SBS];
    int i = blockIdx.x * SBS + threadIdx.x;
    int v = (i < n) ? cnt[i] : 0;
    if (i < n) dinv[i] = rsqrtf((float)v + 1.0f);   // + self-loop
    sh[threadIdx.x] = v;
    __syncthreads();
    for (int off = 1; off < SBS; off <<= 1) {
        int t = (threadIdx.x >= off) ? sh[threadIdx.x - off] : 0;
        __syncthreads();
        sh[threadIdx.x] += t;
        __syncthreads();
    }
    if (i < n) incl[i] = sh[threadIdx.x];
    if (threadIdx.x == SBS - 1) bsum[blockIdx.x] = sh[SBS - 1];
}

__global__ __launch_bounds__(SBS) void k_scan2(int* bsum, int nb) {
    __shared__ int sh[SBS];
    int t = threadIdx.x;
    int v = (t < nb) ? bsum[t] : 0;
    sh[t] = v;
    __syncthreads();
    for (int off = 1; off < SBS; off <<= 1) {
        int u = (t >= off) ? sh[t - off] : 0;
        __syncthreads();
        sh[t] += u;
        __syncthreads();
    }
    if (t < nb) bsum[t] = sh[t] - v;                // exclusive
}

__global__ __launch_bounds__(256) void k_scan3(const int* __restrict__ incl,
                                               const int* __restrict__ bsum,
                                               int* rowptr, int n) {
    int i = blockIdx.x * 256 + threadIdx.x;
    if (i < n) rowptr[i + 1] = incl[i] + bsum[i / SBS];
    if (i == 0) rowptr[0] = 0;
}

__global__ __launch_bounds__(256) void k_fill(const int* __restrict__ src,
                                              const int* __restrict__ dst,
                                              const int* __restrict__ rowptr,
                                              const float* __restrict__ dinv,
                                              int* cursor, int* csrc,
                                              float* cw, int e) {
    int i = blockIdx.x * 256 + threadIdx.x;
    if (i >= e) return;
    int s = __ldg(src + i), d = __ldg(dst + i);
    int pos = __ldg(rowptr + d) + atomicAdd(cursor + d, 1);
    csrc[pos] = s;
    cw[pos] = __ldg(dinv + s) * __ldg(dinv + d);
}

// Fold eval-BN + bias into per-feature affine: y = relu(agg_total*A + B)
__global__ void k_bn(const float* b0, const float* gg0, const float* be0,
                     const float* m0, const float* v0,
                     const float* b1, const float* gg1, const float* be1,
                     const float* m1, const float* v1,
                     const float* b2, const float* gg2, const float* be2,
                     const float* m2, const float* v2,
                     float* A, float* B) {
    int t = threadIdx.x;
    if (t >= 3 * H) return;
    int l = t >> 6, f = t & 63;
    const float* bs[3] = {b0, b1, b2};
    const float* gs[3] = {gg0, gg1, gg2};
    const float* es[3] = {be0, be1, be2};
    const float* ms[3] = {m0, m1, m2};
    const float* vs[3] = {v0, v1, v2};
    float a = gs[l][f] * rsqrtf(vs[l][f] + BN_EPS);
    A[t] = a;
    B[t] = es[l][f] + (bs[l][f] - ms[l][f]) * a;
}

// ------------- GEMM: C[n,64] = X[n,K] @ W[K,64], packed f32x2 FMA ----------
// Block tile 128 rows x 64 cols, 256 threads, thread tile 8 rows x 4 cols.
// XsT[k][row] transposed -> ulonglong2 loads give natural row-pairs.
// Wd[k][2n]=(w,w) duplicated -> LDS.64 gives broadcast pair, banks 2*tx.
template<int K>
__global__ __launch_bounds__(256) void k_gemm(const float* __restrict__ X,
                                              const float* __restrict__ W,
                                              float* __restrict__ Y, int n) {
    __shared__ float XsT[KB][132];   // [k][row], stride 132 (=4 mod 32)
    __shared__ float Wd [KB][132];   // [k][dup cols 0..127]
    const int t = threadIdx.x;
    const int tx = t & 15;           // cols: tx + 16*j, j=0..3
    const int ty = t >> 4;           // rows: 8*ty .. 8*ty+7
    const int row0 = blockIdx.x * 128;

    unsigned long long acc[4][4];    // [rowpair][colslot]
#pragma unroll
    for (int p = 0; p < 4; p++)
#pragma unroll
        for (int j = 0; j < 4; j++) acc[p][j] = 0ull;

    for (int kb = 0; kb < K; kb += KB) {
        // X tile transposed: 128 rows x KB k = 1024 float4, 4 per thread
#pragma unroll
        for (int i = 0; i < 4; i++) {
            int idx = t + i * 256;
            int r = idx & 127;
            int kc = idx >> 7;       // 0..7 float4 chunk
            int gr = row0 + r;
            float4 v = make_float4(0.f, 0.f, 0.f, 0.f);
            if (gr < n) v = *(const float4*)(X + (size_t)gr * K + kb + kc * 4);
            XsT[kc * 4 + 0][r] = v.x;
            XsT[kc * 4 + 1][r] = v.y;
            XsT[kc * 4 + 2][r] = v.z;
            XsT[kc * 4 + 3][r] = v.w;
        }
        // W duplicated: KB x 64 = 2048 scalars, 8 per thread
#pragma unroll
        for (int i = 0; i < 8; i++) {
            int idx = t + i * 256;
            int k = idx >> 6, nn = idx & 63;
            float w = W[(size_t)(kb + k) * H + nn];
            Wd[k][2 * nn] = w;
            Wd[k][2 * nn + 1] = w;
        }
        __syncthreads();

#pragma unroll
        for (int k = 0; k < KB; k++) {
            ulonglong2 xa = *(const ulonglong2*)&XsT[k][ty * 8];      // rows 0-3
            ulonglong2 xb = *(const ulonglong2*)&XsT[k][ty * 8 + 4];  // rows 4-7
            unsigned long long w0 = *(const unsigned long long*)&Wd[k][2 * (tx)];
            unsigned long long w1 = *(const unsigned long long*)&Wd[k][2 * (tx + 16)];
            unsigned long long w2 = *(const unsigned long long*)&Wd[k][2 * (tx + 32)];
            unsigned long long w3 = *(const unsigned long long*)&Wd[k][2 * (tx + 48)];
            ffma2(acc[0][0], xa.x, w0); ffma2(acc[0][1], xa.x, w1);
            ffma2(acc[0][2], xa.x, w2); ffma2(acc[0][3], xa.x, w3);
            ffma2(acc[1][0], xa.y, w0); ffma2(acc[1][1], xa.y, w1);
            ffma2(acc[1][2], xa.y, w2); ffma2(acc[1][3], xa.y, w3);
            ffma2(acc[2][0], xb.x, w0); ffma2(acc[2][1], xb.x, w1);
            ffma2(acc[2][2], xb.x, w2); ffma2(acc[2][3], xb.x, w3);
            ffma2(acc[3][0], xb.y, w0); ffma2(acc[3][1], xb.y, w1);
            ffma2(acc[3][2], xb.y, w2); ffma2(acc[3][3], xb.y, w3);
        }
        __syncthreads();
    }

#pragma unroll
    for (int p = 0; p < 4; p++) {
        int r = row0 + ty * 8 + 2 * p;
#pragma unroll
        for (int j = 0; j < 4; j++) {
            int nn = tx + 16 * j;
            if (r < n)     Y[(size_t)r * H + nn]       = u64_lo(acc[p][j]);
            if (r + 1 < n) Y[(size_t)(r + 1) * H + nn] = u64_hi(acc[p][j]);
        }
    }
}

// --------- fused gather-aggregate + self-loop + BN + ReLU (+pool) ----------
// Warp per node: 16 float4 columns x 2 edge parities; 4-deep load batching.
template<bool POOL>
__global__ __launch_bounds__(256) void k_gather(const int* __restrict__ rowptr,
                                                const int* __restrict__ csrc,
                                                const float* __restrict__ cw,
                                                const float* __restrict__ dinv,
                                                const float4* __restrict__ h,
                                                float4* __restrict__ y,
                                                const float* __restrict__ bnA,
                                                const float* __restrict__ bnB,
                                                const int* __restrict__ batch,
                                                float4* pooled, int n) {
    int node = blockIdx.x * 8 + (threadIdx.x >> 5);
    if (node >= n) return;
    int lane = threadIdx.x & 31;
    int c = lane & 15, p = lane >> 4;
    int beg = __ldg(rowptr + node), end = __ldg(rowptr + node + 1);

    float4 acc = make_float4(0.f, 0.f, 0.f, 0.f);
    int j = beg + p;
#pragma unroll 1
    for (; j + 6 < end; j += 8) {
        int s0 = __ldg(csrc + j);
        int s1 = __ldg(csrc + j + 2);
        int s2 = __ldg(csrc + j + 4);
        int s3 = __ldg(csrc + j + 6);
        float w0 = __ldg(cw + j);
        float w1 = __ldg(cw + j + 2);
        float w2 = __ldg(cw + j + 4);
        float w3 = __ldg(cw + j + 6);
        float4 v0 = __ldg(h + (size_t)s0 * HV + c);
        float4 v1 = __ldg(h + (size_t)s1 * HV + c);
        float4 v2 = __ldg(h + (size_t)s2 * HV + c);
        float4 v3 = __ldg(h + (size_t)s3 * HV + c);
        acc.x = fmaf(v0.x, w0, acc.x); acc.y = fmaf(v0.y, w0, acc.y);
        acc.z = fmaf(v0.z, w0, acc.z); acc.w = fmaf(v0.w, w0, acc.w);
        acc.x = fmaf(v1.x, w1, acc.x); acc.y = fmaf(v1.y, w1, acc.y);
        acc.z = fmaf(v1.z, w1, acc.z); acc.w = fmaf(v1.w, w1, acc.w);
        acc.x = fmaf(v2.x, w2, acc.x); acc.y = fmaf(v2.y, w2, acc.y);
        acc.z = fmaf(v2.z, w2, acc.z); acc.w = fmaf(v2.w, w2, acc.w);
        acc.x = fmaf(v3.x, w3, acc.x); acc.y = fmaf(v3.y, w3, acc.y);
        acc.z = fmaf(v3.z, w3, acc.z); acc.w = fmaf(v3.w, w3, acc.w);
    }
#pragma unroll 1
    for (; j < end; j += 2) {
        int s = __ldg(csrc + j);
        float w = __ldg(cw + j);
        float4 v = __ldg(h + (size_t)s * HV + c);
        acc.x = fmaf(v.x, w, acc.x);
        acc.y = fmaf(v.y, w, acc.y);
        acc.z = fmaf(v.z, w, acc.z);
        acc.w = fmaf(v.w, w, acc.w);
    }
    acc.x += __shfl_down_sync(0xffffffffu, acc.x, 16);
    acc.y += __shfl_down_sync(0xffffffffu, acc.y, 16);
    acc.z += __shfl_down_sync(0xffffffffu, acc.z, 16);
    acc.w += __shfl_down_sync(0xffffffffu, acc.w, 16);

    if (p == 0) {
        float di = __ldg(dinv + node);
        float d2 = di * di;                       // self-loop weight
        float4 hv = __ldg(h + (size_t)node * HV + c);
        float4 A = *(const float4*)(bnA + c * 4);
        float4 B = *(const float4*)(bnB + c * 4);
        float4 o;
        o.x = fmaxf(fmaf(fmaf(hv.x, d2, acc.x), A.x, B.x), 0.f);
        o.y = fmaxf(fmaf(fmaf(hv.y, d2, acc.y), A.y, B.y), 0.f);
        o.z = fmaxf(fmaf(fmaf(hv.z, d2, acc.z), A.z, B.z), 0.f);
        o.w = fmaxf(fmaf(fmaf(hv.w, d2, acc.w), A.w, B.w), 0.f);
        y[(size_t)node * HV + c] = o;
        if (POOL)
            red_add_v4(pooled + (size_t)__ldg(batch + node) * HV + c, o);
    }
}

// ---------------- readout MLP ----------------
__global__ __launch_bounds__(256) void k_mlp(const float* __restrict__ pooled,
                                             const float* __restrict__ l1w,
                                             const float* __restrict__ l1b,
                                             const float* __restrict__ l2w,
                                             const float* __restrict__ l2b,
                                             float* __restrict__ out, int g) {
    __shared__ float4 W1[64 * 8];
    __shared__ float  B1[32];
    __shared__ float  W2[64];
    __shared__ float  B2[2];
    int t = threadIdx.x;
    for (int idx = t; idx < 512; idx += 256) W1[idx] = ((const float4*)l1w)[idx];
    if (t < 32) B1[t] = l1b[t];
    if (t < 64) W2[t] = l2w[t];
    if (t < 2)  B2[t] = l2b[t];
    __syncthreads();

    int gi = blockIdx.x * 256 + t;
    if (gi >= g) return;

    float hid[32];
#pragma unroll
    for (int j = 0; j < 32; j++) hid[j] = B1[j];
    for (int k = 0; k < 64; k++) {
        float p = pooled[(size_t)gi * 64 + k];
#pragma unroll
        for (int jj = 0; jj < 8; jj++) {
            float4 w = W1[k * 8 + jj];
            hid[jj * 4 + 0] = fmaf(p, w.x, hid[jj * 4 + 0]);
            hid[jj * 4 + 1] = fmaf(p, w.y, hid[jj * 4 + 1]);
            hid[jj * 4 + 2] = fmaf(p, w.z, hid[jj * 4 + 2]);
            hid[jj * 4 + 3] = fmaf(p, w.w, hid[jj * 4 + 3]);
        }
    }
    float o0 = B2[0], o1 = B2[1];
#pragma unroll
    for (int j = 0; j < 32; j++) {
        float hj = fmaxf(hid[j], 0.f);
        o0 = fmaf(hj, W2[j * 2 + 0], o0);
        o1 = fmaf(hj, W2[j * 2 + 1], o1);
    }
    out[(size_t)gi * 2 + 0] = o0;
    out[(size_t)gi * 2 + 1] = o1;
}

// ---------------- launch ----------------
extern "C" void kernel_launch(void* const* d_in, const int* in_sizes, int n_in,
                              void* d_out, int out_size) {
    const float* x     = (const float*)d_in[0];
    const int*   ei    = (const int*)  d_in[1];
    const int*   batch = (const int*)  d_in[2];
    const float* w0 = (const float*)d_in[3];
    const float* b0 = (const float*)d_in[4];
    const float* w1 = (const float*)d_in[5];
    const float* b1 = (const float*)d_in[6];
    const float* w2 = (const float*)d_in[7];
    const float* b2 = (const float*)d_in[8];
    const float* gg0 = (const float*)d_in[9],  *be0 = (const float*)d_in[10];
    const float* m0  = (const float*)d_in[11], *v0  = (const float*)d_in[12];
    const float* gg1 = (const float*)d_in[13], *be1 = (const float*)d_in[14];
    const float* m1  = (const float*)d_in[15], *v1  = (const float*)d_in[16];
    const float* gg2 = (const float*)d_in[17], *be2 = (const float*)d_in[18];
    const float* m2  = (const float*)d_in[19], *v2  = (const float*)d_in[20];
    const float* l1w = (const float*)d_in[21], *l1b = (const float*)d_in[22];
    const float* l2w = (const float*)d_in[23], *l2b = (const float*)d_in[24];

    const int n = in_sizes[0] / F_IN;
    const int e = in_sizes[1] / 2;
    const int g = out_size / 2;
    if (n <= 0) return;

    float4 *bufA, *bufB, *pooled;
    float  *dinv, *cw, *bnA, *bnB;
    int    *degcnt, *cursor, *incl, *bsum, *rowptr, *csrc;
    cudaGetSymbolAddress((void**)&bufA,   g_bufA);
    cudaGetSymbolAddress((void**)&bufB,   g_bufB);
    cudaGetSymbolAddress((void**)&pooled, g_pooled);
    cudaGetSymbolAddress((void**)&dinv,   g_dinv);
    cudaGetSymbolAddress((void**)&degcnt, g_degcnt);
    cudaGetSymbolAddress((void**)&cursor, g_cursor);
    cudaGetSymbolAddress((void**)&incl,   g_incl);
    cudaGetSymbolAddress((void**)&bsum,   g_bsum);
    cudaGetSymbolAddress((void**)&rowptr, g_rowptr);
    cudaGetSymbolAddress((void**)&csrc,   g_csrc);
    cudaGetSymbolAddress((void**)&cw,     g_cw);
    cudaGetSymbolAddress((void**)&bnA,    g_bnA);
    cudaGetSymbolAddress((void**)&bnB,    g_bnB);

    const int* src = ei;
    const int* dst = ei + e;

    const int TB = 256;
    const int gInit = (((n > g * HV) ? n : g * HV) + TB - 1) / TB;
    const int gEdge = (e + TB - 1) / TB;
    const int gNode = (n + TB - 1) / TB;
    const int nbScan = (n + SBS - 1) / SBS;
    const int gGemm = (n + 127) / 128;
    const int gGath = (n + 7) / 8;

    // Launch order puts layer-0 GEMM at index 3 (ncu -s captures it).
    k_init <<<gInit, TB>>>(pooled, degcnt, cursor, n, g);          // 0
    k_hist <<<gEdge, TB>>>(dst, degcnt, e);                        // 1
    k_bn   <<<1, 3 * H>>>(b0, gg0, be0, m0, v0, b1, gg1, be1, m1, v1,
                          b2, gg2, be2, m2, v2, bnA, bnB);         // 2
    k_gemm<F_IN><<<gGemm, TB>>>(x, w0, (float*)bufA, n);           // 3
    k_scan1<<<nbScan, SBS>>>(degcnt, incl, bsum, dinv, n);         // 4
    k_scan2<<<1, SBS>>>(bsum, nbScan);                             // 5
    k_scan3<<<gNode, TB>>>(incl, bsum, rowptr, n);                 // 6
    k_fill <<<gEdge, TB>>>(src, dst, rowptr, dinv, cursor, csrc, cw, e); // 7

    // ----- layer 0 gather -----
    k_gather<false><<<gGath, TB>>>(rowptr, csrc, cw, dinv, bufA, bufB,
                                   bnA, bnB, batch, pooled, n);
    // ----- layer 1 -----
    k_gemm<H><<<gGemm, TB>>>((const float*)bufB, w1, (float*)bufA, n);
    k_gather<false><<<gGath, TB>>>(rowptr, csrc, cw, dinv, bufA, bufB,
                                   bnA + H, bnB + H, batch, pooled, n);
    // ----- layer 2 (pool fused) -----
    k_gemm<H><<<gGemm, TB>>>((const float*)bufB, w2, (float*)bufA, n);
    k_gather<true><<<gGath, TB>>>(rowptr, csrc, cw, dinv, bufA, bufB,
                                  bnA + 2 * H, bnB + 2 * H, batch, pooled, n);

    // ----- readout MLP -----
    k_mlp<<<(g + TB - 1) / TB, TB>>>((const float*)pooled, l1w, l1b, l2w, l2b,
                                     (float*)d_out, g);
}

// round 5
// speedup vs baseline: 2.7322x; 1.2390x over previous
#include <cuda_runtime.h>
#include <cuda_bf16.h>
#include <math.h>
#include <stdint.h>

#define F_IN   128
#define H      64
#define HV     16          // float4 chunks per feature row
#define N_MAX  100000
#define E_MAX  1700000
#define G_MAX  4096
#define BN_EPS 1e-5f
#define SBS    1024

// ---------------- scratch (device globals: allocation-free) ----------------
__device__ float4 g_bufA[(size_t)N_MAX * HV];
__device__ float4 g_bufB[(size_t)N_MAX * HV];
__device__ float4 g_pooled[(size_t)G_MAX * HV];
__device__ float  g_dinv[N_MAX];
__device__ int    g_degcnt[N_MAX];
__device__ int    g_cursor[N_MAX];
__device__ int    g_incl[N_MAX];
__device__ int    g_bsum[SBS];
__device__ int    g_rowptr[N_MAX + 1];
__device__ int    g_csrc[E_MAX];
__device__ float  g_cw[E_MAX];
__device__ float  g_bnA[3 * H];
__device__ float  g_bnB[3 * H];

// ---------------- helpers ----------------
__device__ __forceinline__ uint32_t smem_u32(const void* p) {
    uint32_t a;
    asm("{ .reg .u64 t; cvta.to.shared.u64 t, %1; cvt.u32.u64 %0, t; }"
        : "=r"(a) : "l"(p));
    return a;
}
__device__ __forceinline__ void red_add_v4(float4* p, float4 v) {
    asm volatile("red.global.add.v4.f32 [%0], {%1, %2, %3, %4};"
                 :: "l"(p), "f"(v.x), "f"(v.y), "f"(v.z), "f"(v.w)
                 : "memory");
}
__device__ __forceinline__ void ldsm4(uint32_t* r, uint32_t addr) {
    asm volatile("ldmatrix.sync.aligned.m8n8.x4.shared.b16 {%0,%1,%2,%3}, [%4];"
                 : "=r"(r[0]), "=r"(r[1]), "=r"(r[2]), "=r"(r[3]) : "r"(addr));
}
__device__ __forceinline__ void mma_bf16(float* c, const uint32_t* a,
                                         const uint32_t* b) {
    asm volatile(
        "mma.sync.aligned.m16n8k16.row.col.f32.bf16.bf16.f32 "
        "{%0,%1,%2,%3}, {%4,%5,%6,%7}, {%8,%9}, {%0,%1,%2,%3};"
        : "+f"(c[0]), "+f"(c[1]), "+f"(c[2]), "+f"(c[3])
        : "r"(a[0]), "r"(a[1]), "r"(a[2]), "r"(a[3]), "r"(b[0]), "r"(b[1]));
}
__device__ __forceinline__ uint32_t pack_bf2(float lo, float hi) {
    __nv_bfloat162 r = __floats2bfloat162_rn(lo, hi);   // lo->.x, hi->.y
    return *(uint32_t*)&r;
}

// ---------------- setup kernels ----------------
__global__ __launch_bounds__(256) void k_init(float4* pooled, int* degcnt,
                                              int* cursor, int n, int g) {
    int i = blockIdx.x * 256 + threadIdx.x;
    if (i < g * HV) pooled[i] = make_float4(0.f, 0.f, 0.f, 0.f);
    if (i < n) { degcnt[i] = 0; cursor[i] = 0; }
}

__global__ __launch_bounds__(256) void k_hist(const int* __restrict__ dst,
                                              int* degcnt, int e) {
    int i = blockIdx.x * 256 + threadIdx.x;
    if (i < e) atomicAdd(degcnt + __ldg(dst + i), 1);
}

__global__ __launch_bounds__(SBS) void k_scan1(const int* __restrict__ cnt,
                                               int* incl, int* bsum,
                                               float* dinv, int n) {
    __shared__ int sh[SBS];
    int i = blockIdx.x * SBS + threadIdx.x;
    int v = (i < n) ? cnt[i] : 0;
    if (i < n) dinv[i] = rsqrtf((float)v + 1.0f);   // + self-loop
    sh[threadIdx.x] = v;
    __syncthreads();
    for (int off = 1; off < SBS; off <<= 1) {
        int t = (threadIdx.x >= off) ? sh[threadIdx.x - off] : 0;
        __syncthreads();
        sh[threadIdx.x] += t;
        __syncthreads();
    }
    if (i < n) incl[i] = sh[threadIdx.x];
    if (threadIdx.x == SBS - 1) bsum[blockIdx.x] = sh[SBS - 1];
}

__global__ __launch_bounds__(SBS) void k_scan2(int* bsum, int nb) {
    __shared__ int sh[SBS];
    int t = threadIdx.x;
    int v = (t < nb) ? bsum[t] : 0;
    sh[t] = v;
    __syncthreads();
    for (int off = 1; off < SBS; off <<= 1) {
        int u = (t >= off) ? sh[t - off] : 0;
        __syncthreads();
        sh[t] += u;
        __syncthreads();
    }
    if (t < nb) bsum[t] = sh[t] - v;                // exclusive
}

__global__ __launch_bounds__(256) void k_scan3(const int* __restrict__ incl,
                                               const int* __restrict__ bsum,
                                               int* rowptr, int n) {
    int i = blockIdx.x * 256 + threadIdx.x;
    if (i < n) rowptr[i + 1] = incl[i] + bsum[i / SBS];
    if (i == 0) rowptr[0] = 0;
}

__global__ __launch_bounds__(256) void k_fill(const int* __restrict__ src,
                                              const int* __restrict__ dst,
                                              const int* __restrict__ rowptr,
                                              const float* __restrict__ dinv,
                                              int* cursor, int* csrc,
                                              float* cw, int e) {
    int i = blockIdx.x * 256 + threadIdx.x;
    if (i >= e) return;
    int s = __ldg(src + i), d = __ldg(dst + i);
    int pos = __ldg(rowptr + d) + atomicAdd(cursor + d, 1);
    csrc[pos] = s;
    cw[pos] = __ldg(dinv + s) * __ldg(dinv + d);
}

// Fold eval-BN + bias into per-feature affine: y = relu(agg_total*A + B)
__global__ void k_bn(const float* b0, const float* gg0, const float* be0,
                     const float* m0, const float* v0,
                     const float* b1, const float* gg1, const float* be1,
                     const float* m1, const float* v1,
                     const float* b2, const float* gg2, const float* be2,
                     const float* m2, const float* v2,
                     float* A, float* B) {
    int t = threadIdx.x;
    if (t >= 3 * H) return;
    int l = t >> 6, f = t & 63;
    const float* bs[3] = {b0, b1, b2};
    const float* gs[3] = {gg0, gg1, gg2};
    const float* es[3] = {be0, be1, be2};
    const float* ms[3] = {m0, m1, m2};
    const float* vs[3] = {v0, v1, v2};
    float a = gs[l][f] * rsqrtf(vs[l][f] + BN_EPS);
    A[t] = a;
    B[t] = es[l][f] + (bs[l][f] - ms[l][f]) * a;
}

// ---- HMMA GEMM: Y[n,64] = X[n,K] @ W[K,64], bf16 hi/lo split (3 terms) ----
// CTA: 128 rows x 64 cols, 8 warps, warp owns m16 x n64.
// Smem: A/B as bf16 with +8-elem row padding -> conflict-free ldmatrix.
template<int K>
__global__ __launch_bounds__(256) void k_gemm_mma(const float* __restrict__ X,
                                                  const float* __restrict__ W,
                                                  float* __restrict__ Y, int n) {
    extern __shared__ __align__(16) char smem[];
    constexpr int LD = K + 8;                     // bf16 elems per row
    __nv_bfloat16* Ah = (__nv_bfloat16*)smem;     // [128][LD]
    __nv_bfloat16* Al = Ah + 128 * LD;
    __nv_bfloat16* Bh = Al + 128 * LD;            // [64][LD]
    __nv_bfloat16* Bl = Bh + 64 * LD;

    const int t = threadIdx.x;
    const int wid = t >> 5, lane = t & 31;
    const int row0 = blockIdx.x * 128;

    // ---- A: 128 x K fp32 -> bf16 hi/lo ----
#pragma unroll
    for (int i = 0; i < 128 * (K / 4) / 256; i++) {
        int idx = t + i * 256;
        int r = idx / (K / 4);
        int k0 = (idx % (K / 4)) * 4;
        int gr = row0 + r;
        float4 v = make_float4(0.f, 0.f, 0.f, 0.f);
        if (gr < n) v = *(const float4*)(X + (size_t)gr * K + k0);
        float hx = __bfloat162float(__float2bfloat16(v.x));
        float hy = __bfloat162float(__float2bfloat16(v.y));
        float hz = __bfloat162float(__float2bfloat16(v.z));
        float hw = __bfloat162float(__float2bfloat16(v.w));
        uint2 hp, lp;
        hp.x = pack_bf2(v.x, v.y);
        hp.y = pack_bf2(v.z, v.w);
        lp.x = pack_bf2(v.x - hx, v.y - hy);
        lp.y = pack_bf2(v.z - hz, v.w - hw);
        *(uint2*)&Ah[r * LD + k0] = hp;
        *(uint2*)&Al[r * LD + k0] = lp;
    }
    // ---- B[nn][k] = W[k][nn] -> bf16 hi/lo ----
#pragma unroll
    for (int i = 0; i < K * 64 / 256; i++) {
        int idx = t + i * 256;
        int k = idx >> 6, nn = idx & 63;
        float w = W[(size_t)k * 64 + nn];
        float hh = __bfloat162float(__float2bfloat16(w));
        Bh[nn * LD + k] = __float2bfloat16(w);
        Bl[nn * LD + k] = __float2bfloat16(w - hh);
    }
    __syncthreads();

    // ---- MMA mainloop ----
    float c[8][4];
#pragma unroll
    for (int j = 0; j < 8; j++) {
        c[j][0] = 0.f; c[j][1] = 0.f; c[j][2] = 0.f; c[j][3] = 0.f;
    }

    const int m0 = wid * 16;
    const uint32_t sAh = smem_u32(Ah), sAl = smem_u32(Al);
    const uint32_t sBh = smem_u32(Bh), sBl = smem_u32(Bl);
    // A ldmatrix lane addressing: rows m0+(lane&15), k offset +8 for hi lanes
    uint32_t aOff = (uint32_t)(((m0 + (lane & 15)) * LD + ((lane >> 4) << 3)) * 2);
    // B: n = (lane&7) + 8*(lane>>4)  (pair of n-tiles), k offset +8 if lane&8
    uint32_t bOff = (uint32_t)((((lane & 7) + ((lane >> 4) << 3)) * LD
                                + (lane & 8)) * 2);

#pragma unroll
    for (int kc = 0; kc < K / 16; kc++) {
        uint32_t ah[4], al[4];
        ldsm4(ah, sAh + aOff + kc * 32);
        ldsm4(al, sAl + aOff + kc * 32);
#pragma unroll
        for (int j = 0; j < 4; j++) {
            uint32_t off = bOff + (uint32_t)(j * 16 * LD * 2) + kc * 32;
            uint32_t bh[4], bl[4];
            ldsm4(bh, sBh + off);
            ldsm4(bl, sBl + off);
            mma_bf16(c[2 * j],     ah, bh);
            mma_bf16(c[2 * j],     ah, bl + 0);      // wrong? no:
            mma_bf16(c[2 * j],     al, bh);
            mma_bf16(c[2 * j + 1], ah, bh + 2);
            mma_bf16(c[2 * j + 1], ah, bl + 2);
            mma_bf16(c[2 * j + 1], al, bh + 2);
        }
    }
    // fix: second term above must use bl low half for tile 2j
    // (handled correctly: bl+0 is tile 2j, bl+2 is tile 2j+1)

    // ---- store C ----
    int cr = lane >> 2, cc = (lane & 3) * 2;
    int r0g = row0 + m0 + cr;
    int r1g = r0g + 8;
    if (r0g < n) {
#pragma unroll
        for (int j = 0; j < 8; j++)
            *(float2*)(Y + (size_t)r0g * 64 + j * 8 + cc)
                = make_float2(c[j][0], c[j][1]);
    }
    if (r1g < n) {
#pragma unroll
        for (int j = 0; j < 8; j++)
            *(float2*)(Y + (size_t)r1g * 64 + j * 8 + cc)
                = make_float2(c[j][2], c[j][3]);
    }
}

// --------- fused gather-aggregate + self-loop + BN + ReLU (+pool) ----------
// Warp per node: 16 float4 columns x 2 edge parities (round-2 proven form).
template<bool POOL>
__global__ __launch_bounds__(256) void k_gather(const int* __restrict__ rowptr,
                                                const int* __restrict__ csrc,
                                                const float* __restrict__ cw,
                                                const float* __restrict__ dinv,
                                                const float4* __restrict__ h,
                                                float4* __restrict__ y,
                                                const float* __restrict__ bnA,
                                                const float* __restrict__ bnB,
                                                const int* __restrict__ batch,
                                                float4* pooled, int n) {
    int node = blockIdx.x * 8 + (threadIdx.x >> 5);
    if (node >= n) return;
    int lane = threadIdx.x & 31;
    int c = lane & 15, p = lane >> 4;
    int beg = __ldg(rowptr + node), end = __ldg(rowptr + node + 1);

    float4 acc = make_float4(0.f, 0.f, 0.f, 0.f);
#pragma unroll 2
    for (int j = beg + p; j < end; j += 2) {
        int s = __ldg(csrc + j);
        float w = __ldg(cw + j);
        float4 v = __ldg(h + (size_t)s * HV + c);
        acc.x = fmaf(v.x, w, acc.x);
        acc.y = fmaf(v.y, w, acc.y);
        acc.z = fmaf(v.z, w, acc.z);
        acc.w = fmaf(v.w, w, acc.w);
    }
    acc.x += __shfl_down_sync(0xffffffffu, acc.x, 16);
    acc.y += __shfl_down_sync(0xffffffffu, acc.y, 16);
    acc.z += __shfl_down_sync(0xffffffffu, acc.z, 16);
    acc.w += __shfl_down_sync(0xffffffffu, acc.w, 16);

    if (p == 0) {
        float di = __ldg(dinv + node);
        float d2 = di * di;                       // self-loop weight
        float4 hv = __ldg(h + (size_t)node * HV + c);
        float4 A = *(const float4*)(bnA + c * 4);
        float4 B = *(const float4*)(bnB + c * 4);
        float4 o;
        o.x = fmaxf(fmaf(fmaf(hv.x, d2, acc.x), A.x, B.x), 0.f);
        o.y = fmaxf(fmaf(fmaf(hv.y, d2, acc.y), A.y, B.y), 0.f);
        o.z = fmaxf(fmaf(fmaf(hv.z, d2, acc.z), A.z, B.z), 0.f);
        o.w = fmaxf(fmaf(fmaf(hv.w, d2, acc.w), A.w, B.w), 0.f);
        y[(size_t)node * HV + c] = o;
        if (POOL)
            red_add_v4(pooled + (size_t)__ldg(batch + node) * HV + c, o);
    }
}

// ---------------- readout MLP ----------------
__global__ __launch_bounds__(256) void k_mlp(const float* __restrict__ pooled,
                                             const float* __restrict__ l1w,
                                             const float* __restrict__ l1b,
                                             const float* __restrict__ l2w,
                                             const float* __restrict__ l2b,
                                             float* __restrict__ out, int g) {
    __shared__ float4 W1[64 * 8];
    __shared__ float  B1[32];
    __shared__ float  W2[64];
    __shared__ float  B2[2];
    int t = threadIdx.x;
    for (int idx = t; idx < 512; idx += 256) W1[idx] = ((const float4*)l1w)[idx];
    if (t < 32) B1[t] = l1b[t];
    if (t < 64) W2[t] = l2w[t];
    if (t < 2)  B2[t] = l2b[t];
    __syncthreads();

    int gi = blockIdx.x * 256 + t;
    if (gi >= g) return;

    float hid[32];
#pragma unroll
    for (int j = 0; j < 32; j++) hid[j] = B1[j];
    for (int k = 0; k < 64; k++) {
        float p = pooled[(size_t)gi * 64 + k];
#pragma unroll
        for (int jj = 0; jj < 8; jj++) {
            float4 w = W1[k * 8 + jj];
            hid[jj * 4 + 0] = fmaf(p, w.x, hid[jj * 4 + 0]);
            hid[jj * 4 + 1] = fmaf(p, w.y, hid[jj * 4 + 1]);
            hid[jj * 4 + 2] = fmaf(p, w.z, hid[jj * 4 + 2]);
            hid[jj * 4 + 3] = fmaf(p, w.w, hid[jj * 4 + 3]);
        }
    }
    float o0 = B2[0], o1 = B2[1];
#pragma unroll
    for (int j = 0; j < 32; j++) {
        float hj = fmaxf(hid[j], 0.f);
        o0 = fmaf(hj, W2[j * 2 + 0], o0);
        o1 = fmaf(hj, W2[j * 2 + 1], o1);
    }
    out[(size_t)gi * 2 + 0] = o0;
    out[(size_t)gi * 2 + 1] = o1;
}

// ---------------- launch ----------------
extern "C" void kernel_launch(void* const* d_in, const int* in_sizes, int n_in,
                              void* d_out, int out_size) {
    const float* x     = (const float*)d_in[0];
    const int*   ei    = (const int*)  d_in[1];
    const int*   batch = (const int*)  d_in[2];
    const float* w0 = (const float*)d_in[3];
    const float* b0 = (const float*)d_in[4];
    const float* w1 = (const float*)d_in[5];
    const float* b1 = (const float*)d_in[6];
    const float* w2 = (const float*)d_in[7];
    const float* b2 = (const float*)d_in[8];
    const float* gg0 = (const float*)d_in[9],  *be0 = (const float*)d_in[10];
    const float* m0  = (const float*)d_in[11], *v0  = (const float*)d_in[12];
    const float* gg1 = (const float*)d_in[13], *be1 = (const float*)d_in[14];
    const float* m1  = (const float*)d_in[15], *v1  = (const float*)d_in[16];
    const float* gg2 = (const float*)d_in[17], *be2 = (const float*)d_in[18];
    const float* m2  = (const float*)d_in[19], *v2  = (const float*)d_in[20];
    const float* l1w = (const float*)d_in[21], *l1b = (const float*)d_in[22];
    const float* l2w = (const float*)d_in[23], *l2b = (const float*)d_in[24];

    const int n = in_sizes[0] / F_IN;
    const int e = in_sizes[1] / 2;
    const int g = out_size / 2;
    if (n <= 0) return;

    float4 *bufA, *bufB, *pooled;
    float  *dinv, *cw, *bnA, *bnB;
    int    *degcnt, *cursor, *incl, *bsum, *rowptr, *csrc;
    cudaGetSymbolAddress((void**)&bufA,   g_bufA);
    cudaGetSymbolAddress((void**)&bufB,   g_bufB);
    cudaGetSymbolAddress((void**)&pooled, g_pooled);
    cudaGetSymbolAddress((void**)&dinv,   g_dinv);
    cudaGetSymbolAddress((void**)&degcnt, g_degcnt);
    cudaGetSymbolAddress((void**)&cursor, g_cursor);
    cudaGetSymbolAddress((void**)&incl,   g_incl);
    cudaGetSymbolAddress((void**)&bsum,   g_bsum);
    cudaGetSymbolAddress((void**)&rowptr, g_rowptr);
    cudaGetSymbolAddress((void**)&csrc,   g_csrc);
    cudaGetSymbolAddress((void**)&cw,     g_cw);
    cudaGetSymbolAddress((void**)&bnA,    g_bnA);
    cudaGetSymbolAddress((void**)&bnB,    g_bnB);

    const int* src = ei;
    const int* dst = ei + e;

    const int TB = 256;
    const int gInit = (((n > g * HV) ? n : g * HV) + TB - 1) / TB;
    const int gEdge = (e + TB - 1) / TB;
    const int gNode = (n + TB - 1) / TB;
    const int nbScan = (n + SBS - 1) / SBS;
    const int gGemm = (n + 127) / 128;
    const int gGath = (n + 7) / 8;

    const int SM128 = (128 * (F_IN + 8) * 2 + 64 * (F_IN + 8) * 2) * 2; // 104448
    const int SM64  = (128 * (H + 8) * 2 + 64 * (H + 8) * 2) * 2;       // 55296
    cudaFuncSetAttribute(k_gemm_mma<F_IN>,
                         cudaFuncAttributeMaxDynamicSharedMemorySize, SM128);
    cudaFuncSetAttribute(k_gemm_mma<H>,
                         cudaFuncAttributeMaxDynamicSharedMemorySize, SM64);

    // Launch order puts layer-0 GEMM at index 3 (ncu -s 5 captures nearby).
    k_init <<<gInit, TB>>>(pooled, degcnt, cursor, n, g);          // 0
    k_hist <<<gEdge, TB>>>(dst, degcnt, e);                        // 1
    k_bn   <<<1, 3 * H>>>(b0, gg0, be0, m0, v0, b1, gg1, be1, m1, v1,
                          b2, gg2, be2, m2, v2, bnA, bnB);         // 2
    k_gemm_mma<F_IN><<<gGemm, TB, SM128>>>(x, w0, (float*)bufA, n); // 3
    k_scan1<<<nbScan, SBS>>>(degcnt, incl, bsum, dinv, n);         // 4
    k_scan2<<<1, SBS>>>(bsum, nbScan);                             // 5
    k_scan3<<<gNode, TB>>>(incl, bsum, rowptr, n);                 // 6
    k_fill <<<gEdge, TB>>>(src, dst, rowptr, dinv, cursor, csrc, cw, e); // 7

    // ----- layer 0 gather -----
    k_gather<false><<<gGath, TB>>>(rowptr, csrc, cw, dinv, bufA, bufB,
                                   bnA, bnB, batch, pooled, n);
    // ----- layer 1 -----
    k_gemm_mma<H><<<gGemm, TB, SM64>>>((const float*)bufB, w1, (float*)bufA, n);
    k_gather<false><<<gGath, TB>>>(rowptr, csrc, cw, dinv, bufA, bufB,
                                   bnA + H, bnB + H, batch, pooled, n);
    // ----- layer 2 (pool fused) -----
    k_gemm_mma<H><<<gGemm, TB, SM64>>>((const float*)bufB, w2, (float*)bufA, n);
    k_gather<true><<<gGath, TB>>>(rowptr, csrc, cw, dinv, bufA, bufB,
                                  bnA + 2 * H, bnB + 2 * H, batch, pooled, n);

    // ----- readout MLP -----
    k_mlp<<<(g + TB - 1) / TB, TB>>>((const float*)pooled, l1w, l1b, l2w, l2b,
                                     (float*)d_out, g);
}

// round 6
// speedup vs baseline: 2.7939x; 1.0226x over previous
#include <cuda_runtime.h>
#include <cuda_bf16.h>
#include <math.h>
#include <stdint.h>

#define F_IN   128
#define H      64
#define HV     16          // float4 chunks per feature row
#define N_MAX  100000
#define E_MAX  1700000
#define G_MAX  4096
#define BN_EPS 1e-5f
#define SBS    1024

// ---------------- scratch (device globals: allocation-free) ----------------
__device__ float4 g_bufA[(size_t)N_MAX * HV];
__device__ float4 g_bufB[(size_t)N_MAX * HV];
__device__ float4 g_pooled[(size_t)G_MAX * HV];
__device__ float  g_dinv[N_MAX];
__device__ int    g_degcnt[N_MAX];
__device__ int    g_cursor[N_MAX];
__device__ int    g_incl[N_MAX];
__device__ int    g_bsum[SBS];
__device__ int    g_rowptr[N_MAX + 1];
__device__ int    g_csrc[E_MAX];
__device__ float  g_cw[E_MAX];
__device__ float  g_bnA[3 * H];
__device__ float  g_bnB[3 * H];

// ---------------- helpers ----------------
__device__ __forceinline__ uint32_t smem_u32(const void* p) {
    uint32_t a;
    asm("{ .reg .u64 t; cvta.to.shared.u64 t, %1; cvt.u32.u64 %0, t; }"
        : "=r"(a) : "l"(p));
    return a;
}
__device__ __forceinline__ void red_add_v4(float4* p, float4 v) {
    asm volatile("red.global.add.v4.f32 [%0], {%1, %2, %3, %4};"
                 :: "l"(p), "f"(v.x), "f"(v.y), "f"(v.z), "f"(v.w)
                 : "memory");
}
__device__ __forceinline__ void ldsm4(uint32_t* r, uint32_t addr) {
    asm volatile("ldmatrix.sync.aligned.m8n8.x4.shared.b16 {%0,%1,%2,%3}, [%4];"
                 : "=r"(r[0]), "=r"(r[1]), "=r"(r[2]), "=r"(r[3]) : "r"(addr));
}
__device__ __forceinline__ void mma_bf16(float* c, const uint32_t* a,
                                         const uint32_t* b) {
    asm volatile(
        "mma.sync.aligned.m16n8k16.row.col.f32.bf16.bf16.f32 "
        "{%0,%1,%2,%3}, {%4,%5,%6,%7}, {%8,%9}, {%0,%1,%2,%3};"
        : "+f"(c[0]), "+f"(c[1]), "+f"(c[2]), "+f"(c[3])
        : "r"(a[0]), "r"(a[1]), "r"(a[2]), "r"(a[3]), "r"(b[0]), "r"(b[1]));
}
__device__ __forceinline__ uint32_t pack_bf2(float lo, float hi) {
    __nv_bfloat162 r = __floats2bfloat162_rn(lo, hi);   // lo->.x, hi->.y
    return *(uint32_t*)&r;
}

// ---------------- setup kernels ----------------
__global__ __launch_bounds__(256) void k_init(float4* pooled, int* degcnt,
                                              int* cursor, int n, int g) {
    int i = blockIdx.x * 256 + threadIdx.x;
    if (i < g * HV) pooled[i] = make_float4(0.f, 0.f, 0.f, 0.f);
    if (i < n) { degcnt[i] = 0; cursor[i] = 0; }
}

__global__ __launch_bounds__(256) void k_hist(const int* __restrict__ dst,
                                              int* degcnt, int e) {
    int i = blockIdx.x * 256 + threadIdx.x;
    if (i < e) atomicAdd(degcnt + __ldg(dst + i), 1);
}

__global__ __launch_bounds__(SBS) void k_scan1(const int* __restrict__ cnt,
                                               int* incl, int* bsum,
                                               float* dinv, int n) {
    __shared__ int sh[SBS];
    int i = blockIdx.x * SBS + threadIdx.x;
    int v = (i < n) ? cnt[i] : 0;
    if (i < n) dinv[i] = rsqrtf((float)v + 1.0f);   // + self-loop
    sh[threadIdx.x] = v;
    __syncthreads();
    for (int off = 1; off < SBS; off <<= 1) {
        int t = (threadIdx.x >= off) ? sh[threadIdx.x - off] : 0;
        __syncthreads();
        sh[threadIdx.x] += t;
        __syncthreads();
    }
    if (i < n) incl[i] = sh[threadIdx.x];
    if (threadIdx.x == SBS - 1) bsum[blockIdx.x] = sh[SBS - 1];
}

__global__ __launch_bounds__(SBS) void k_scan2(int* bsum, int nb) {
    __shared__ int sh[SBS];
    int t = threadIdx.x;
    int v = (t < nb) ? bsum[t] : 0;
    sh[t] = v;
    __syncthreads();
    for (int off = 1; off < SBS; off <<= 1) {
        int u = (t >= off) ? sh[t - off] : 0;
        __syncthreads();
        sh[t] += u;
        __syncthreads();
    }
    if (t < nb) bsum[t] = sh[t] - v;                // exclusive
}

__global__ __launch_bounds__(256) void k_scan3(const int* __restrict__ incl,
                                               const int* __restrict__ bsum,
                                               int* rowptr, int n) {
    int i = blockIdx.x * 256 + threadIdx.x;
    if (i < n) rowptr[i + 1] = incl[i] + bsum[i / SBS];
    if (i == 0) rowptr[0] = 0;
}

__global__ __launch_bounds__(256) void k_fill(const int* __restrict__ src,
                                              const int* __restrict__ dst,
                                              const int* __restrict__ rowptr,
                                              const float* __restrict__ dinv,
                                              int* cursor, int* csrc,
                                              float* cw, int e) {
    int i = blockIdx.x * 256 + threadIdx.x;
    if (i >= e) return;
    int s = __ldg(src + i), d = __ldg(dst + i);
    int pos = __ldg(rowptr + d) + atomicAdd(cursor + d, 1);
    csrc[pos] = s;
    cw[pos] = __ldg(dinv + s) * __ldg(dinv + d);
}

// Fold eval-BN + bias into per-feature affine: y = relu(agg_total*A + B)
__global__ void k_bn(const float* b0, const float* gg0, const float* be0,
                     const float* m0, const float* v0,
                     const float* b1, const float* gg1, const float* be1,
                     const float* m1, const float* v1,
                     const float* b2, const float* gg2, const float* be2,
                     const float* m2, const float* v2,
                     float* A, float* B) {
    int t = threadIdx.x;
    if (t >= 3 * H) return;
    int l = t >> 6, f = t & 63;
    const float* bs[3] = {b0, b1, b2};
    const float* gs[3] = {gg0, gg1, gg2};
    const float* es[3] = {be0, be1, be2};
    const float* ms[3] = {m0, m1, m2};
    const float* vs[3] = {v0, v1, v2};
    float a = gs[l][f] * rsqrtf(vs[l][f] + BN_EPS);
    A[t] = a;
    B[t] = es[l][f] + (bs[l][f] - ms[l][f]) * a;
}

// ---- HMMA GEMM: Y[n,64] = X[n,K] @ W[K,64], bf16 hi/lo split (3 terms) ----
// CTA: 128 rows x 64 cols, 512 threads / 16 warps; warp (w) owns
// m16 rows (w>>1) x n32 cols ((w&1)*32). Doubled warps per CTA raise
// occupancy and loads-in-flight (the kernel is DRAM-stream-bound on X).
template<int K>
__global__ __launch_bounds__(512) void k_gemm_mma(const float* __restrict__ X,
                                                  const float* __restrict__ W,
                                                  float* __restrict__ Y, int n) {
    extern __shared__ __align__(16) char smem[];
    constexpr int LD = K + 8;                     // bf16 elems per row
    __nv_bfloat16* Ah = (__nv_bfloat16*)smem;     // [128][LD]
    __nv_bfloat16* Al = Ah + 128 * LD;
    __nv_bfloat16* Bh = Al + 128 * LD;            // [64][LD]
    __nv_bfloat16* Bl = Bh + 64 * LD;

    const int t = threadIdx.x;
    const int wid = t >> 5, lane = t & 31;
    const int row0 = blockIdx.x * 128;

    // ---- A: 128 x K fp32 -> bf16 hi/lo ----
#pragma unroll
    for (int i = 0; i < 128 * (K / 4) / 512; i++) {
        int idx = t + i * 512;
        int r = idx / (K / 4);
        int k0 = (idx % (K / 4)) * 4;
        int gr = row0 + r;
        float4 v = make_float4(0.f, 0.f, 0.f, 0.f);
        if (gr < n) v = *(const float4*)(X + (size_t)gr * K + k0);
        float hx = __bfloat162float(__float2bfloat16(v.x));
        float hy = __bfloat162float(__float2bfloat16(v.y));
        float hz = __bfloat162float(__float2bfloat16(v.z));
        float hw = __bfloat162float(__float2bfloat16(v.w));
        uint2 hp, lp;
        hp.x = pack_bf2(v.x, v.y);
        hp.y = pack_bf2(v.z, v.w);
        lp.x = pack_bf2(v.x - hx, v.y - hy);
        lp.y = pack_bf2(v.z - hz, v.w - hw);
        *(uint2*)&Ah[r * LD + k0] = hp;
        *(uint2*)&Al[r * LD + k0] = lp;
    }
    // ---- B[nn][k] = W[k][nn] -> bf16 hi/lo ----
#pragma unroll
    for (int i = 0; i < K * 64 / 512; i++) {
        int idx = t + i * 512;
        int k = idx >> 6, nn = idx & 63;
        float w = W[(size_t)k * 64 + nn];
        float hh = __bfloat162float(__float2bfloat16(w));
        Bh[nn * LD + k] = __float2bfloat16(w);
        Bl[nn * LD + k] = __float2bfloat16(w - hh);
    }
    __syncthreads();

    // ---- MMA mainloop: warp tile m16 x n32 ----
    float c[4][4];
#pragma unroll
    for (int j = 0; j < 4; j++) {
        c[j][0] = 0.f; c[j][1] = 0.f; c[j][2] = 0.f; c[j][3] = 0.f;
    }

    const int m0 = (wid >> 1) * 16;
    const int nb = (wid & 1) * 32;
    const uint32_t sAh = smem_u32(Ah), sAl = smem_u32(Al);
    const uint32_t sBh = smem_u32(Bh), sBl = smem_u32(Bl);
    uint32_t aOff = (uint32_t)(((m0 + (lane & 15)) * LD + ((lane >> 4) << 3)) * 2);
    uint32_t bOff = (uint32_t)(((nb + (lane & 7) + ((lane >> 4) << 3)) * LD
                                + (lane & 8)) * 2);

#pragma unroll
    for (int kc = 0; kc < K / 16; kc++) {
        uint32_t ah[4], al[4];
        ldsm4(ah, sAh + aOff + kc * 32);
        ldsm4(al, sAl + aOff + kc * 32);
#pragma unroll
        for (int j = 0; j < 2; j++) {
            uint32_t off = bOff + (uint32_t)(j * 16 * LD * 2) + kc * 32;
            uint32_t bh[4], bl[4];
            ldsm4(bh, sBh + off);
            ldsm4(bl, sBl + off);
            mma_bf16(c[2 * j],     ah, bh);
            mma_bf16(c[2 * j],     ah, bl);
            mma_bf16(c[2 * j],     al, bh);
            mma_bf16(c[2 * j + 1], ah, bh + 2);
            mma_bf16(c[2 * j + 1], ah, bl + 2);
            mma_bf16(c[2 * j + 1], al, bh + 2);
        }
    }

    // ---- store C (tile jj covers cols nb + jj*8) ----
    int cr = lane >> 2, cc = (lane & 3) * 2;
    int r0g = row0 + m0 + cr;
    int r1g = r0g + 8;
    if (r0g < n) {
#pragma unroll
        for (int jj = 0; jj < 4; jj++)
            *(float2*)(Y + (size_t)r0g * 64 + nb + jj * 8 + cc)
                = make_float2(c[jj][0], c[jj][1]);
    }
    if (r1g < n) {
#pragma unroll
        for (int jj = 0; jj < 4; jj++)
            *(float2*)(Y + (size_t)r1g * 64 + nb + jj * 8 + cc)
                = make_float2(c[jj][2], c[jj][3]);
    }
}

// --------- fused gather-aggregate + self-loop + BN + ReLU (+pool) ----------
// Warp per node: 16 float4 columns x 2 edge parities (round-2 proven form).
template<bool POOL>
__global__ __launch_bounds__(256) void k_gather(const int* __restrict__ rowptr,
                                                const int* __restrict__ csrc,
                                                const float* __restrict__ cw,
                                                const float* __restrict__ dinv,
                                                const float4* __restrict__ h,
                                                float4* __restrict__ y,
                                                const float* __restrict__ bnA,
                                                const float* __restrict__ bnB,
                                                const int* __restrict__ batch,
                                                float4* pooled, int n) {
    int node = blockIdx.x * 8 + (threadIdx.x >> 5);
    if (node >= n) return;
    int lane = threadIdx.x & 31;
    int c = lane & 15, p = lane >> 4;
    int beg = __ldg(rowptr + node), end = __ldg(rowptr + node + 1);

    float4 acc = make_float4(0.f, 0.f, 0.f, 0.f);
#pragma unroll 2
    for (int j = beg + p; j < end; j += 2) {
        int s = __ldg(csrc + j);
        float w = __ldg(cw + j);
        float4 v = __ldg(h + (size_t)s * HV + c);
        acc.x = fmaf(v.x, w, acc.x);
        acc.y = fmaf(v.y, w, acc.y);
        acc.z = fmaf(v.z, w, acc.z);
        acc.w = fmaf(v.w, w, acc.w);
    }
    acc.x += __shfl_down_sync(0xffffffffu, acc.x, 16);
    acc.y += __shfl_down_sync(0xffffffffu, acc.y, 16);
    acc.z += __shfl_down_sync(0xffffffffu, acc.z, 16);
    acc.w += __shfl_down_sync(0xffffffffu, acc.w, 16);

    if (p == 0) {
        float di = __ldg(dinv + node);
        float d2 = di * di;                       // self-loop weight
        float4 hv = __ldg(h + (size_t)node * HV + c);
        float4 A = *(const float4*)(bnA + c * 4);
        float4 B = *(const float4*)(bnB + c * 4);
        float4 o;
        o.x = fmaxf(fmaf(fmaf(hv.x, d2, acc.x), A.x, B.x), 0.f);
        o.y = fmaxf(fmaf(fmaf(hv.y, d2, acc.y), A.y, B.y), 0.f);
        o.z = fmaxf(fmaf(fmaf(hv.z, d2, acc.z), A.z, B.z), 0.f);
        o.w = fmaxf(fmaf(fmaf(hv.w, d2, acc.w), A.w, B.w), 0.f);
        y[(size_t)node * HV + c] = o;
        if (POOL)
            red_add_v4(pooled + (size_t)__ldg(batch + node) * HV + c, o);
    }
}

// ---------------- readout MLP ----------------
__global__ __launch_bounds__(256) void k_mlp(const float* __restrict__ pooled,
                                             const float* __restrict__ l1w,
                                             const float* __restrict__ l1b,
                                             const float* __restrict__ l2w,
                                             const float* __restrict__ l2b,
                                             float* __restrict__ out, int g) {
    __shared__ float4 W1[64 * 8];
    __shared__ float  B1[32];
    __shared__ float  W2[64];
    __shared__ float  B2[2];
    int t = threadIdx.x;
    for (int idx = t; idx < 512; idx += 256) W1[idx] = ((const float4*)l1w)[idx];
    if (t < 32) B1[t] = l1b[t];
    if (t < 64) W2[t] = l2w[t];
    if (t < 2)  B2[t] = l2b[t];
    __syncthreads();

    int gi = blockIdx.x * 256 + t;
    if (gi >= g) return;

    float hid[32];
#pragma unroll
    for (int j = 0; j < 32; j++) hid[j] = B1[j];
    for (int k = 0; k < 64; k++) {
        float p = pooled[(size_t)gi * 64 + k];
#pragma unroll
        for (int jj = 0; jj < 8; jj++) {
            float4 w = W1[k * 8 + jj];
            hid[jj * 4 + 0] = fmaf(p, w.x, hid[jj * 4 + 0]);
            hid[jj * 4 + 1] = fmaf(p, w.y, hid[jj * 4 + 1]);
            hid[jj * 4 + 2] = fmaf(p, w.z, hid[jj * 4 + 2]);
            hid[jj * 4 + 3] = fmaf(p, w.w, hid[jj * 4 + 3]);
        }
    }
    float o0 = B2[0], o1 = B2[1];
#pragma unroll
    for (int j = 0; j < 32; j++) {
        float hj = fmaxf(hid[j], 0.f);
        o0 = fmaf(hj, W2[j * 2 + 0], o0);
        o1 = fmaf(hj, W2[j * 2 + 1], o1);
    }
    out[(size_t)gi * 2 + 0] = o0;
    out[(size_t)gi * 2 + 1] = o1;
}

// ---------------- launch ----------------
extern "C" void kernel_launch(void* const* d_in, const int* in_sizes, int n_in,
                              void* d_out, int out_size) {
    const float* x     = (const float*)d_in[0];
    const int*   ei    = (const int*)  d_in[1];
    const int*   batch = (const int*)  d_in[2];
    const float* w0 = (const float*)d_in[3];
    const float* b0 = (const float*)d_in[4];
    const float* w1 = (const float*)d_in[5];
    const float* b1 = (const float*)d_in[6];
    const float* w2 = (const float*)d_in[7];
    const float* b2 = (const float*)d_in[8];
    const float* gg0 = (const float*)d_in[9],  *be0 = (const float*)d_in[10];
    const float* m0  = (const float*)d_in[11], *v0  = (const float*)d_in[12];
    const float* gg1 = (const float*)d_in[13], *be1 = (const float*)d_in[14];
    const float* m1  = (const float*)d_in[15], *v1  = (const float*)d_in[16];
    const float* gg2 = (const float*)d_in[17], *be2 = (const float*)d_in[18];
    const float* m2  = (const float*)d_in[19], *v2  = (const float*)d_in[20];
    const float* l1w = (const float*)d_in[21], *l1b = (const float*)d_in[22];
    const float* l2w = (const float*)d_in[23], *l2b = (const float*)d_in[24];

    const int n = in_sizes[0] / F_IN;
    const int e = in_sizes[1] / 2;
    const int g = out_size / 2;
    if (n <= 0) return;

    float4 *bufA, *bufB, *pooled;
    float  *dinv, *cw, *bnA, *bnB;
    int    *degcnt, *cursor, *incl, *bsum, *rowptr, *csrc;
    cudaGetSymbolAddress((void**)&bufA,   g_bufA);
    cudaGetSymbolAddress((void**)&bufB,   g_bufB);
    cudaGetSymbolAddress((void**)&pooled, g_pooled);
    cudaGetSymbolAddress((void**)&dinv,   g_dinv);
    cudaGetSymbolAddress((void**)&degcnt, g_degcnt);
    cudaGetSymbolAddress((void**)&cursor, g_cursor);
    cudaGetSymbolAddress((void**)&incl,   g_incl);
    cudaGetSymbolAddress((void**)&bsum,   g_bsum);
    cudaGetSymbolAddress((void**)&rowptr, g_rowptr);
    cudaGetSymbolAddress((void**)&csrc,   g_csrc);
    cudaGetSymbolAddress((void**)&cw,     g_cw);
    cudaGetSymbolAddress((void**)&bnA,    g_bnA);
    cudaGetSymbolAddress((void**)&bnB,    g_bnB);

    const int* src = ei;
    const int* dst = ei + e;

    const int TB = 256;
    const int gInit = (((n > g * HV) ? n : g * HV) + TB - 1) / TB;
    const int gEdge = (e + TB - 1) / TB;
    const int gNode = (n + TB - 1) / TB;
    const int nbScan = (n + SBS - 1) / SBS;
    const int gGemm = (n + 127) / 128;
    const int gGath = (n + 7) / 8;

    const int SM128 = (128 * (F_IN + 8) * 2 + 64 * (F_IN + 8) * 2) * 2; // 104448
    const int SM64  = (128 * (H + 8) * 2 + 64 * (H + 8) * 2) * 2;       // 55296
    cudaFuncSetAttribute(k_gemm_mma<F_IN>,
                         cudaFuncAttributeMaxDynamicSharedMemorySize, SM128);
    cudaFuncSetAttribute(k_gemm_mma<H>,
                         cudaFuncAttributeMaxDynamicSharedMemorySize, SM64);

    // Side stream + events for fork/join overlap (host resources, created
    // once; launched work is identical on every call).
    static cudaStream_t s_pre = nullptr;
    static cudaEvent_t ev_fork = nullptr, ev_join = nullptr;
    if (s_pre == nullptr) {
        cudaStreamCreateWithFlags(&s_pre, cudaStreamNonBlocking);
        cudaEventCreateWithFlags(&ev_fork, cudaEventDisableTiming);
        cudaEventCreateWithFlags(&ev_join, cudaEventDisableTiming);
    }

    // ---- fork: graph preprocessing on s_pre, concurrent with gemm0 ----
    cudaEventRecord(ev_fork, 0);
    cudaStreamWaitEvent(s_pre, ev_fork, 0);
    k_init <<<gInit, TB, 0, s_pre>>>(pooled, degcnt, cursor, n, g);
    k_hist <<<gEdge, TB, 0, s_pre>>>(dst, degcnt, e);
    k_scan1<<<nbScan, SBS, 0, s_pre>>>(degcnt, incl, bsum, dinv, n);
    k_scan2<<<1, SBS, 0, s_pre>>>(bsum, nbScan);
    k_scan3<<<gNode, TB, 0, s_pre>>>(incl, bsum, rowptr, n);
    k_fill <<<gEdge, TB, 0, s_pre>>>(src, dst, rowptr, dinv, cursor, csrc, cw, e);
    cudaEventRecord(ev_join, s_pre);

    // ---- main stream: BN fold + layer-0 GEMM (independent of the graph) ----
    k_bn<<<1, 3 * H>>>(b0, gg0, be0, m0, v0, b1, gg1, be1, m1, v1,
                       b2, gg2, be2, m2, v2, bnA, bnB);
    k_gemm_mma<F_IN><<<gGemm, 512, SM128>>>(x, w0, (float*)bufA, n);

    // ---- join ----
    cudaStreamWaitEvent(0, ev_join, 0);

    // ----- layer 0 gather -----
    k_gather<false><<<gGath, TB>>>(rowptr, csrc, cw, dinv, bufA, bufB,
                                   bnA, bnB, batch, pooled, n);
    // ----- layer 1 -----
    k_gemm_mma<H><<<gGemm, 512, SM64>>>((const float*)bufB, w1, (float*)bufA, n);
    k_gather<false><<<gGath, TB>>>(rowptr, csrc, cw, dinv, bufA, bufB,
                                   bnA + H, bnB + H, batch, pooled, n);
    // ----- layer 2 (pool fused) -----
    k_gemm_mma<H><<<gGemm, 512, SM64>>>((const float*)bufB, w2, (float*)bufA, n);
    k_gather<true><<<gGath, TB>>>(rowptr, csrc, cw, dinv, bufA, bufB,
                                  bnA + 2 * H, bnB + 2 * H, batch, pooled, n);

    // ----- readout MLP -----
    k_mlp<<<(g + TB - 1) / TB, TB>>>((const float*)pooled, l1w, l1b, l2w, l2b,
                                     (float*)d_out, g);
}

// round 7
// speedup vs baseline: 2.8642x; 1.0252x over previous
#include <cuda_runtime.h>
#include <cuda_bf16.h>
#include <math.h>
#include <stdint.h>

#define F_IN   128
#define H      64
#define HV     16
#define N_MAX  100000
#define E_MAX  1700000
#define G_MAX  4096
#define BN_EPS 1e-5f
#define SBS    1024

// ---------------- scratch (device globals: allocation-free) ----------------
__device__ __nv_bfloat16 g_bufA[(size_t)N_MAX * H];   // bf16 activations
__device__ __nv_bfloat16 g_bufB[(size_t)N_MAX * H];
__device__ float4 g_pooled[(size_t)G_MAX * HV];
__device__ float  g_dinv[N_MAX];
__device__ int    g_degcnt[N_MAX];
__device__ int    g_cursor[N_MAX];
__device__ int    g_incl[N_MAX];
__device__ int    g_bsum[SBS];
__device__ int    g_rowptr[N_MAX + 1];
__device__ int    g_csrc[E_MAX];
__device__ float  g_cw[E_MAX];
__device__ float  g_bnA[3 * H];
__device__ float  g_bnB[3 * H];

// ---------------- helpers ----------------
__device__ __forceinline__ uint32_t smem_u32(const void* p) {
    uint32_t a;
    asm("{ .reg .u64 t; cvta.to.shared.u64 t, %1; cvt.u32.u64 %0, t; }"
        : "=r"(a) : "l"(p));
    return a;
}
__device__ __forceinline__ void red_add_v4(float4* p, float4 v) {
    asm volatile("red.global.add.v4.f32 [%0], {%1, %2, %3, %4};"
                 :: "l"(p), "f"(v.x), "f"(v.y), "f"(v.z), "f"(v.w)
                 : "memory");
}
__device__ __forceinline__ void ldsm4(uint32_t* r, uint32_t addr) {
    asm volatile("ldmatrix.sync.aligned.m8n8.x4.shared.b16 {%0,%1,%2,%3}, [%4];"
                 : "=r"(r[0]), "=r"(r[1]), "=r"(r[2]), "=r"(r[3]) : "r"(addr));
}
__device__ __forceinline__ void mma_bf16(float* c, const uint32_t* a,
                                         const uint32_t* b) {
    asm volatile(
        "mma.sync.aligned.m16n8k16.row.col.f32.bf16.bf16.f32 "
        "{%0,%1,%2,%3}, {%4,%5,%6,%7}, {%8,%9}, {%0,%1,%2,%3};"
        : "+f"(c[0]), "+f"(c[1]), "+f"(c[2]), "+f"(c[3])
        : "r"(a[0]), "r"(a[1]), "r"(a[2]), "r"(a[3]), "r"(b[0]), "r"(b[1]));
}
__device__ __forceinline__ uint32_t pack_bf2(float lo, float hi) {
    __nv_bfloat162 r = __floats2bfloat162_rn(lo, hi);
    return *(uint32_t*)&r;
}

// ---------------- setup kernels ----------------
__global__ __launch_bounds__(256) void k_init(float4* pooled, int* degcnt,
                                              int* cursor, int n, int g) {
    int i = blockIdx.x * 256 + threadIdx.x;
    if (i < g * HV) pooled[i] = make_float4(0.f, 0.f, 0.f, 0.f);
    if (i < n) { degcnt[i] = 0; cursor[i] = 0; }
}

__global__ __launch_bounds__(256) void k_hist(const int* __restrict__ dst,
                                              int* degcnt, int e) {
    int i = blockIdx.x * 256 + threadIdx.x;
    if (i < e) atomicAdd(degcnt + __ldg(dst + i), 1);
}

__global__ __launch_bounds__(SBS) void k_scan1(const int* __restrict__ cnt,
                                               int* incl, int* bsum,
                                               float* dinv, int n) {
    __shared__ int sh[SBS];
    int i = blockIdx.x * SBS + threadIdx.x;
    int v = (i < n) ? cnt[i] : 0;
    if (i < n) dinv[i] = rsqrtf((float)v + 1.0f);
    sh[threadIdx.x] = v;
    __syncthreads();
    for (int off = 1; off < SBS; off <<= 1) {
        int t = (threadIdx.x >= off) ? sh[threadIdx.x - off] : 0;
        __syncthreads();
        sh[threadIdx.x] += t;
        __syncthreads();
    }
    if (i < n) incl[i] = sh[threadIdx.x];
    if (threadIdx.x == SBS - 1) bsum[blockIdx.x] = sh[SBS - 1];
}

__global__ __launch_bounds__(SBS) void k_scan2(int* bsum, int nb) {
    __shared__ int sh[SBS];
    int t = threadIdx.x;
    int v = (t < nb) ? bsum[t] : 0;
    sh[t] = v;
    __syncthreads();
    for (int off = 1; off < SBS; off <<= 1) {
        int u = (t >= off) ? sh[t - off] : 0;
        __syncthreads();
        sh[t] += u;
        __syncthreads();
    }
    if (t < nb) bsum[t] = sh[t] - v;
}

__global__ __launch_bounds__(256) void k_scan3(const int* __restrict__ incl,
                                               const int* __restrict__ bsum,
                                               int* rowptr, int n) {
    int i = blockIdx.x * 256 + threadIdx.x;
    if (i < n) rowptr[i + 1] = incl[i] + bsum[i / SBS];
    if (i == 0) rowptr[0] = 0;
}

__global__ __launch_bounds__(256) void k_fill(const int* __restrict__ src,
                                              const int* __restrict__ dst,
                                              const int* __restrict__ rowptr,
                                              const float* __restrict__ dinv,
                                              int* cursor, int* csrc,
                                              float* cw, int e) {
    int i = blockIdx.x * 256 + threadIdx.x;
    if (i >= e) return;
    int s = __ldg(src + i), d = __ldg(dst + i);
    int pos = __ldg(rowptr + d) + atomicAdd(cursor + d, 1);
    csrc[pos] = s;
    cw[pos] = __ldg(dinv + s) * __ldg(dinv + d);
}

__global__ void k_bn(const float* b0, const float* gg0, const float* be0,
                     const float* m0, const float* v0,
                     const float* b1, const float* gg1, const float* be1,
                     const float* m1, const float* v1,
                     const float* b2, const float* gg2, const float* be2,
                     const float* m2, const float* v2,
                     float* A, float* B) {
    int t = threadIdx.x;
    if (t >= 3 * H) return;
    int l = t >> 6, f = t & 63;
    const float* bs[3] = {b0, b1, b2};
    const float* gs[3] = {gg0, gg1, gg2};
    const float* es[3] = {be0, be1, be2};
    const float* ms[3] = {m0, m1, m2};
    const float* vs[3] = {v0, v1, v2};
    float a = gs[l][f] * rsqrtf(vs[l][f] + BN_EPS);
    A[t] = a;
    B[t] = es[l][f] + (bs[l][f] - ms[l][f]) * a;
}

// ---- layer-0 GEMM: fp32 X, bf16 hi/lo split (3 terms), bf16 output --------
// CTA 128 rows x 64 cols, 512 threads / 16 warps, warp tile m16 x n32.
template<int K>
__global__ __launch_bounds__(512) void k_gemm_f32(const float* __restrict__ X,
                                                  const float* __restrict__ W,
                                                  __nv_bfloat16* __restrict__ Y,
                                                  int n) {
    extern __shared__ __align__(16) char smem[];
    constexpr int LD = K + 8;
    __nv_bfloat16* Ah = (__nv_bfloat16*)smem;
    __nv_bfloat16* Al = Ah + 128 * LD;
    __nv_bfloat16* Bh = Al + 128 * LD;
    __nv_bfloat16* Bl = Bh + 64 * LD;

    const int t = threadIdx.x;
    const int wid = t >> 5, lane = t & 31;
    const int row0 = blockIdx.x * 128;

#pragma unroll
    for (int i = 0; i < 128 * (K / 4) / 512; i++) {
        int idx = t + i * 512;
        int r = idx / (K / 4);
        int k0 = (idx % (K / 4)) * 4;
        int gr = row0 + r;
        float4 v = make_float4(0.f, 0.f, 0.f, 0.f);
        if (gr < n) v = *(const float4*)(X + (size_t)gr * K + k0);
        float hx = __bfloat162float(__float2bfloat16(v.x));
        float hy = __bfloat162float(__float2bfloat16(v.y));
        float hz = __bfloat162float(__float2bfloat16(v.z));
        float hw = __bfloat162float(__float2bfloat16(v.w));
        uint2 hp, lp;
        hp.x = pack_bf2(v.x, v.y);
        hp.y = pack_bf2(v.z, v.w);
        lp.x = pack_bf2(v.x - hx, v.y - hy);
        lp.y = pack_bf2(v.z - hz, v.w - hw);
        *(uint2*)&Ah[r * LD + k0] = hp;
        *(uint2*)&Al[r * LD + k0] = lp;
    }
#pragma unroll
    for (int i = 0; i < K * 64 / 512; i++) {
        int idx = t + i * 512;
        int k = idx >> 6, nn = idx & 63;
        float w = W[(size_t)k * 64 + nn];
        float hh = __bfloat162float(__float2bfloat16(w));
        Bh[nn * LD + k] = __float2bfloat16(w);
        Bl[nn * LD + k] = __float2bfloat16(w - hh);
    }
    __syncthreads();

    float c[4][4];
#pragma unroll
    for (int j = 0; j < 4; j++) {
        c[j][0] = 0.f; c[j][1] = 0.f; c[j][2] = 0.f; c[j][3] = 0.f;
    }
    const int m0 = (wid >> 1) * 16;
    const int nb = (wid & 1) * 32;
    const uint32_t sAh = smem_u32(Ah), sAl = smem_u32(Al);
    const uint32_t sBh = smem_u32(Bh), sBl = smem_u32(Bl);
    uint32_t aOff = (uint32_t)(((m0 + (lane & 15)) * LD + ((lane >> 4) << 3)) * 2);
    uint32_t bOff = (uint32_t)(((nb + (lane & 7) + ((lane >> 4) << 3)) * LD
                                + (lane & 8)) * 2);

#pragma unroll
    for (int kc = 0; kc < K / 16; kc++) {
        uint32_t ah[4], al[4];
        ldsm4(ah, sAh + aOff + kc * 32);
        ldsm4(al, sAl + aOff + kc * 32);
#pragma unroll
        for (int j = 0; j < 2; j++) {
            uint32_t off = bOff + (uint32_t)(j * 16 * LD * 2) + kc * 32;
            uint32_t bh[4], bl[4];
            ldsm4(bh, sBh + off);
            ldsm4(bl, sBl + off);
            mma_bf16(c[2 * j],     ah, bh);
            mma_bf16(c[2 * j],     ah, bl);
            mma_bf16(c[2 * j],     al, bh);
            mma_bf16(c[2 * j + 1], ah, bh + 2);
            mma_bf16(c[2 * j + 1], ah, bl + 2);
            mma_bf16(c[2 * j + 1], al, bh + 2);
        }
    }

    int cr = lane >> 2, cc = (lane & 3) * 2;
    int r0g = row0 + m0 + cr;
    int r1g = r0g + 8;
    if (r0g < n) {
#pragma unroll
        for (int jj = 0; jj < 4; jj++)
            *(uint32_t*)(Y + (size_t)r0g * 64 + nb + jj * 8 + cc)
                = pack_bf2(c[jj][0], c[jj][1]);
    }
    if (r1g < n) {
#pragma unroll
        for (int jj = 0; jj < 4; jj++)
            *(uint32_t*)(Y + (size_t)r1g * 64 + nb + jj * 8 + cc)
                = pack_bf2(c[jj][2], c[jj][3]);
    }
}

// ---- layers 1/2 GEMM: bf16 X (exact), B hi/lo split (2 terms) -------------
__global__ __launch_bounds__(512) void k_gemm_bf(const __nv_bfloat16* __restrict__ X,
                                                 const float* __restrict__ W,
                                                 __nv_bfloat16* __restrict__ Y,
                                                 int n) {
    constexpr int K = 64;
    extern __shared__ __align__(16) char smem[];
    constexpr int LD = K + 8;
    __nv_bfloat16* Ah = (__nv_bfloat16*)smem;     // [128][LD]
    __nv_bfloat16* Bh = Ah + 128 * LD;            // [64][LD]
    __nv_bfloat16* Bl = Bh + 64 * LD;

    const int t = threadIdx.x;
    const int wid = t >> 5, lane = t & 31;
    const int row0 = blockIdx.x * 128;

    // A: 128 x 64 bf16, uint2 (4 elems) per load: 2048 loads / 512 = 4 each
#pragma unroll
    for (int i = 0; i < 4; i++) {
        int idx = t + i * 512;
        int r = idx >> 4;
        int k0 = (idx & 15) * 4;
        int gr = row0 + r;
        uint2 v = make_uint2(0u, 0u);
        if (gr < n) v = *(const uint2*)(X + (size_t)gr * K + k0);
        *(uint2*)&Ah[r * LD + k0] = v;
    }
#pragma unroll
    for (int i = 0; i < K * 64 / 512; i++) {
        int idx = t + i * 512;
        int k = idx >> 6, nn = idx & 63;
        float w = W[(size_t)k * 64 + nn];
        float hh = __bfloat162float(__float2bfloat16(w));
        Bh[nn * LD + k] = __float2bfloat16(w);
        Bl[nn * LD + k] = __float2bfloat16(w - hh);
    }
    __syncthreads();

    float c[4][4];
#pragma unroll
    for (int j = 0; j < 4; j++) {
        c[j][0] = 0.f; c[j][1] = 0.f; c[j][2] = 0.f; c[j][3] = 0.f;
    }
    const int m0 = (wid >> 1) * 16;
    const int nb = (wid & 1) * 32;
    const uint32_t sAh = smem_u32(Ah);
    const uint32_t sBh = smem_u32(Bh), sBl = smem_u32(Bl);
    uint32_t aOff = (uint32_t)(((m0 + (lane & 15)) * LD + ((lane >> 4) << 3)) * 2);
    uint32_t bOff = (uint32_t)(((nb + (lane & 7) + ((lane >> 4) << 3)) * LD
                                + (lane & 8)) * 2);

#pragma unroll
    for (int kc = 0; kc < K / 16; kc++) {
        uint32_t ah[4];
        ldsm4(ah, sAh + aOff + kc * 32);
#pragma unroll
        for (int j = 0; j < 2; j++) {
            uint32_t off = bOff + (uint32_t)(j * 16 * LD * 2) + kc * 32;
            uint32_t bh[4], bl[4];
            ldsm4(bh, sBh + off);
            ldsm4(bl, sBl + off);
            mma_bf16(c[2 * j],     ah, bh);
            mma_bf16(c[2 * j],     ah, bl);
            mma_bf16(c[2 * j + 1], ah, bh + 2);
            mma_bf16(c[2 * j + 1], ah, bl + 2);
        }
    }

    int cr = lane >> 2, cc = (lane & 3) * 2;
    int r0g = row0 + m0 + cr;
    int r1g = r0g + 8;
    if (r0g < n) {
#pragma unroll
        for (int jj = 0; jj < 4; jj++)
            *(uint32_t*)(Y + (size_t)r0g * 64 + nb + jj * 8 + cc)
                = pack_bf2(c[jj][0], c[jj][1]);
    }
    if (r1g < n) {
#pragma unroll
        for (int jj = 0; jj < 4; jj++)
            *(uint32_t*)(Y + (size_t)r1g * 64 + nb + jj * 8 + cc)
                = pack_bf2(c[jj][2], c[jj][3]);
    }
}

// --------- fused gather (bf16 h) + self-loop + BN + ReLU (+pool) -----------
// Warp per node: 16 lanes x 4 bf16 features, 2 edge parities.
template<bool POOL>
__global__ __launch_bounds__(256) void k_gather(const int* __restrict__ rowptr,
                                                const int* __restrict__ csrc,
                                                const float* __restrict__ cw,
                                                const float* __restrict__ dinv,
                                                const __nv_bfloat16* __restrict__ h,
                                                __nv_bfloat16* __restrict__ y,
                                                const float* __restrict__ bnA,
                                                const float* __restrict__ bnB,
                                                const int* __restrict__ batch,
                                                float4* pooled, int n) {
    int node = blockIdx.x * 8 + (threadIdx.x >> 5);
    if (node >= n) return;
    int lane = threadIdx.x & 31;
    int c = lane & 15, p = lane >> 4;
    int beg = __ldg(rowptr + node), end = __ldg(rowptr + node + 1);

    float4 acc = make_float4(0.f, 0.f, 0.f, 0.f);
#pragma unroll 2
    for (int j = beg + p; j < end; j += 2) {
        int s = __ldg(csrc + j);
        float w = __ldg(cw + j);
        uint2 u = __ldg((const uint2*)(h + (size_t)s * 64) + c);
        float2 f0 = __bfloat1622float2(*(__nv_bfloat162*)&u.x);
        float2 f1 = __bfloat1622float2(*(__nv_bfloat162*)&u.y);
        acc.x = fmaf(f0.x, w, acc.x);
        acc.y = fmaf(f0.y, w, acc.y);
        acc.z = fmaf(f1.x, w, acc.z);
        acc.w = fmaf(f1.y, w, acc.w);
    }
    acc.x += __shfl_down_sync(0xffffffffu, acc.x, 16);
    acc.y += __shfl_down_sync(0xffffffffu, acc.y, 16);
    acc.z += __shfl_down_sync(0xffffffffu, acc.z, 16);
    acc.w += __shfl_down_sync(0xffffffffu, acc.w, 16);

    if (p == 0) {
        float di = __ldg(dinv + node);
        float d2 = di * di;
        uint2 u = __ldg((const uint2*)(h + (size_t)node * 64) + c);
        float2 h0 = __bfloat1622float2(*(__nv_bfloat162*)&u.x);
        float2 h1 = __bfloat1622float2(*(__nv_bfloat162*)&u.y);
        float4 A = *(const float4*)(bnA + c * 4);
        float4 B = *(const float4*)(bnB + c * 4);
        float4 o;
        o.x = fmaxf(fmaf(fmaf(h0.x, d2, acc.x), A.x, B.x), 0.f);
        o.y = fmaxf(fmaf(fmaf(h0.y, d2, acc.y), A.y, B.y), 0.f);
        o.z = fmaxf(fmaf(fmaf(h1.x, d2, acc.z), A.z, B.z), 0.f);
        o.w = fmaxf(fmaf(fmaf(h1.y, d2, acc.w), A.w, B.w), 0.f);
        uint2 ob;
        ob.x = pack_bf2(o.x, o.y);
        ob.y = pack_bf2(o.z, o.w);
        ((uint2*)(y + (size_t)node * 64))[c] = ob;
        if (POOL)
            red_add_v4(pooled + (size_t)__ldg(batch + node) * HV + c, o);
    }
}

// ---------------- readout MLP ----------------
__global__ __launch_bounds__(256) void k_mlp(const float* __restrict__ pooled,
                                             const float* __restrict__ l1w,
                                             const float* __restrict__ l1b,
                                             const float* __restrict__ l2w,
                                             const float* __restrict__ l2b,
                                             float* __restrict__ out, int g) {
    __shared__ float4 W1[64 * 8];
    __shared__ float  B1[32];
    __shared__ float  W2[64];
    __shared__ float  B2[2];
    int t = threadIdx.x;
    for (int idx = t; idx < 512; idx += 256) W1[idx] = ((const float4*)l1w)[idx];
    if (t < 32) B1[t] = l1b[t];
    if (t < 64) W2[t] = l2w[t];
    if (t < 2)  B2[t] = l2b[t];
    __syncthreads();

    int gi = blockIdx.x * 256 + t;
    if (gi >= g) return;

    float hid[32];
#pragma unroll
    for (int j = 0; j < 32; j++) hid[j] = B1[j];
    for (int k = 0; k < 64; k++) {
        float p = pooled[(size_t)gi * 64 + k];
#pragma unroll
        for (int jj = 0; jj < 8; jj++) {
            float4 w = W1[k * 8 + jj];
            hid[jj * 4 + 0] = fmaf(p, w.x, hid[jj * 4 + 0]);
            hid[jj * 4 + 1] = fmaf(p, w.y, hid[jj * 4 + 1]);
            hid[jj * 4 + 2] = fmaf(p, w.z, hid[jj * 4 + 2]);
            hid[jj * 4 + 3] = fmaf(p, w.w, hid[jj * 4 + 3]);
        }
    }
    float o0 = B2[0], o1 = B2[1];
#pragma unroll
    for (int j = 0; j < 32; j++) {
        float hj = fmaxf(hid[j], 0.f);
        o0 = fmaf(hj, W2[j * 2 + 0], o0);
        o1 = fmaf(hj, W2[j * 2 + 1], o1);
    }
    out[(size_t)gi * 2 + 0] = o0;
    out[(size_t)gi * 2 + 1] = o1;
}

// ---------------- launch ----------------
extern "C" void kernel_launch(void* const* d_in, const int* in_sizes, int n_in,
                              void* d_out, int out_size) {
    const float* x     = (const float*)d_in[0];
    const int*   ei    = (const int*)  d_in[1];
    const int*   batch = (const int*)  d_in[2];
    const float* w0 = (const float*)d_in[3];
    const float* b0 = (const float*)d_in[4];
    const float* w1 = (const float*)d_in[5];
    const float* b1 = (const float*)d_in[6];
    const float* w2 = (const float*)d_in[7];
    const float* b2 = (const float*)d_in[8];
    const float* gg0 = (const float*)d_in[9],  *be0 = (const float*)d_in[10];
    const float* m0  = (const float*)d_in[11], *v0  = (const float*)d_in[12];
    const float* gg1 = (const float*)d_in[13], *be1 = (const float*)d_in[14];
    const float* m1  = (const float*)d_in[15], *v1  = (const float*)d_in[16];
    const float* gg2 = (const float*)d_in[17], *be2 = (const float*)d_in[18];
    const float* m2  = (const float*)d_in[19], *v2  = (const float*)d_in[20];
    const float* l1w = (const float*)d_in[21], *l1b = (const float*)d_in[22];
    const float* l2w = (const float*)d_in[23], *l2b = (const float*)d_in[24];

    const int n = in_sizes[0] / F_IN;
    const int e = in_sizes[1] / 2;
    const int g = out_size / 2;
    if (n <= 0) return;

    __nv_bfloat16 *bufA, *bufB;
    float4 *pooled;
    float  *dinv, *cw, *bnA, *bnB;
    int    *degcnt, *cursor, *incl, *bsum, *rowptr, *csrc;
    cudaGetSymbolAddress((void**)&bufA,   g_bufA);
    cudaGetSymbolAddress((void**)&bufB,   g_bufB);
    cudaGetSymbolAddress((void**)&pooled, g_pooled);
    cudaGetSymbolAddress((void**)&dinv,   g_dinv);
    cudaGetSymbolAddress((void**)&degcnt, g_degcnt);
    cudaGetSymbolAddress((void**)&cursor, g_cursor);
    cudaGetSymbolAddress((void**)&incl,   g_incl);
    cudaGetSymbolAddress((void**)&bsum,   g_bsum);
    cudaGetSymbolAddress((void**)&rowptr, g_rowptr);
    cudaGetSymbolAddress((void**)&csrc,   g_csrc);
    cudaGetSymbolAddress((void**)&cw,     g_cw);
    cudaGetSymbolAddress((void**)&bnA,    g_bnA);
    cudaGetSymbolAddress((void**)&bnB,    g_bnB);

    const int* src = ei;
    const int* dst = ei + e;

    const int TB = 256;
    const int gInit = (((n > g * HV) ? n : g * HV) + TB - 1) / TB;
    const int gEdge = (e + TB - 1) / TB;
    const int gNode = (n + TB - 1) / TB;
    const int nbScan = (n + SBS - 1) / SBS;
    const int gGemm = (n + 127) / 128;
    const int gGath = (n + 7) / 8;

    const int SM128 = (128 * (F_IN + 8) * 2 + 64 * (F_IN + 8) * 2) * 2; // 104448
    const int SMBF  = (128 * (H + 8) + 2 * 64 * (H + 8)) * 2;           // 36864
    cudaFuncSetAttribute(k_gemm_f32<F_IN>,
                         cudaFuncAttributeMaxDynamicSharedMemorySize, SM128);
    cudaFuncSetAttribute(k_gemm_bf,
                         cudaFuncAttributeMaxDynamicSharedMemorySize, SMBF);

    static cudaStream_t s_pre = nullptr;
    static cudaEvent_t ev_fork = nullptr, ev_join = nullptr;
    if (s_pre == nullptr) {
        cudaStreamCreateWithFlags(&s_pre, cudaStreamNonBlocking);
        cudaEventCreateWithFlags(&ev_fork, cudaEventDisableTiming);
        cudaEventCreateWithFlags(&ev_join, cudaEventDisableTiming);
    }

    // ---- fork: graph preprocessing concurrent with gemm0 ----
    cudaEventRecord(ev_fork, 0);
    cudaStreamWaitEvent(s_pre, ev_fork, 0);
    k_init <<<gInit, TB, 0, s_pre>>>(pooled, degcnt, cursor, n, g);
    k_hist <<<gEdge, TB, 0, s_pre>>>(dst, degcnt, e);
    k_scan1<<<nbScan, SBS, 0, s_pre>>>(degcnt, incl, bsum, dinv, n);
    k_scan2<<<1, SBS, 0, s_pre>>>(bsum, nbScan);
    k_scan3<<<gNode, TB, 0, s_pre>>>(incl, bsum, rowptr, n);
    k_fill <<<gEdge, TB, 0, s_pre>>>(src, dst, rowptr, dinv, cursor, csrc, cw, e);
    cudaEventRecord(ev_join, s_pre);

    k_bn<<<1, 3 * H>>>(b0, gg0, be0, m0, v0, b1, gg1, be1, m1, v1,
                       b2, gg2, be2, m2, v2, bnA, bnB);
    k_gemm_f32<F_IN><<<gGemm, 512, SM128>>>(x, w0, bufA, n);

    cudaStreamWaitEvent(0, ev_join, 0);

    // ----- layer 0 gather -----
    k_gather<false><<<gGath, TB>>>(rowptr, csrc, cw, dinv, bufA, bufB,
                                   bnA, bnB, batch, pooled, n);
    // ----- layer 1 -----
    k_gemm_bf<<<gGemm, 512, SMBF>>>(bufB, w1, bufA, n);
    k_gather<false><<<gGath, TB>>>(rowptr, csrc, cw, dinv, bufA, bufB,
                                   bnA + H, bnB + H, batch, pooled, n);
    // ----- layer 2 (pool fused) -----
    k_gemm_bf<<<gGemm, 512, SMBF>>>(bufB, w2, bufA, n);
    k_gather<true><<<gGath, TB>>>(rowptr, csrc, cw, dinv, bufA, bufB,
                                  bnA + 2 * H, bnB + 2 * H, batch, pooled, n);

    // ----- readout MLP -----
    k_mlp<<<(g + TB - 1) / TB, TB>>>((const float*)pooled, l1w, l1b, l2w, l2b,
                                     (float*)d_out, g);
}